// round 4
// baseline (speedup 1.0000x reference)
#include <cuda_runtime.h>
#include <cuda_fp16.h>

// Problem constants (fixed by the dataset)
constexpr int NN = 100000;   // nodes
constexpr int EE = 1600000;  // edges
constexpr int DD = 64;       // feature dim
constexpr int GG = 512;      // graphs
constexpr int CC = 10;       // classes
constexpr int LL = 5;        // layers (4 conv layers)
constexpr float BN_EPS = 1e-5f;
constexpr int SCAN_B = 1024;
constexpr int NBLK = (NN + SCAN_B - 1) / SCAN_B;   // 98

// Scratch (device globals; no allocation allowed)
__device__ __align__(16) __half g_u16[NN * DD];   // fp16 activations (also x16 at layer 0)
__device__ float g_t[NN * DD];                    // GEMM1 output (fp32)
__device__ float g_pooled[LL * GG * DD];
__device__ float g_stats[8 * 128];                // per BN: [0..63]=sum, [64..127]=sumsq
__device__ int   g_rowptr[NN + 1];
__device__ int   g_cursor[NN];
__device__ int   g_csr[EE];
__device__ int   g_bsum[NBLK];

// ---------------------------------------------------------------------------
// helpers
// ---------------------------------------------------------------------------
__device__ __forceinline__ void red4(float* p, float4 v) {
    asm volatile("red.global.add.v4.f32 [%0], {%1,%2,%3,%4};"
                 :: "l"(p), "f"(v.x), "f"(v.y), "f"(v.z), "f"(v.w) : "memory");
}

__device__ __forceinline__ float2 f2fma(float2 a, float2 b, float2 c) {
    float2 d;
    asm("{\n\t"
        ".reg .b64 ra, rb, rc, rd;\n\t"
        "mov.b64 ra, {%2, %3};\n\t"
        "mov.b64 rb, {%4, %5};\n\t"
        "mov.b64 rc, {%6, %7};\n\t"
        "fma.rn.f32x2 rd, ra, rb, rc;\n\t"
        "mov.b64 {%0, %1}, rd;\n\t"
        "}"
        : "=f"(d.x), "=f"(d.y)
        : "f"(a.x), "f"(a.y), "f"(b.x), "f"(b.y), "f"(c.x), "f"(c.y));
    return d;
}

__device__ __forceinline__ float4 ldh4(const __half* p) {
    uint2 r = *(const uint2*)p;
    __half2 a = *(__half2*)&r.x;
    __half2 b = *(__half2*)&r.y;
    float2 fa = __half22float2(a), fb = __half22float2(b);
    return make_float4(fa.x, fa.y, fb.x, fb.y);
}

__device__ __forceinline__ void sth4(__half* p, float4 v) {
    uint2 r;
    *(__half2*)&r.x = __floats2half2_rn(v.x, v.y);
    *(__half2*)&r.y = __floats2half2_rn(v.z, v.w);
    *(uint2*)p = r;
}

__device__ __forceinline__ float4 bnrelu4(float4 v, float a0, float a1, float a2, float a3,
                                          float b0, float b1, float b2, float b3) {
    v.x = fmaxf(fmaf(a0, v.x, b0), 0.f);
    v.y = fmaxf(fmaf(a1, v.y, b1), 0.f);
    v.z = fmaxf(fmaf(a2, v.z, b2), 0.f);
    v.w = fmaxf(fmaf(a3, v.w, b3), 0.f);
    return v;
}

// ---------------------------------------------------------------------------
// zero accumulators + degree counters (reuse g_rowptr as count buffer)
// ---------------------------------------------------------------------------
__global__ void zerok(float* __restrict__ pooled, float* __restrict__ stats,
                      int* __restrict__ cnt) {
    int i = blockIdx.x * 256 + threadIdx.x;
    if (i < LL * GG * DD) pooled[i] = 0.f;
    if (i < 8 * 128) stats[i] = 0.f;
    if (i <= NN) cnt[i] = 0;
}

// ---------------------------------------------------------------------------
// CSR build
// ---------------------------------------------------------------------------
__global__ void __launch_bounds__(256) hist_kernel(const int* __restrict__ ei,
                                                   int* __restrict__ cnt) {
    int e = blockIdx.x * 256 + threadIdx.x;
    if (e < EE) atomicAdd(&cnt[ei[EE + e]], 1);
}

__global__ void __launch_bounds__(SCAN_B) scanA_kernel(int* __restrict__ rp,
                                                       int* __restrict__ bsum) {
    __shared__ int sm[SCAN_B];
    int gid = blockIdx.x * SCAN_B + threadIdx.x;
    int v = (gid < NN) ? rp[gid] : 0;
    sm[threadIdx.x] = v;
    __syncthreads();
    for (int off = 1; off < SCAN_B; off <<= 1) {
        int t = (threadIdx.x >= off) ? sm[threadIdx.x - off] : 0;
        __syncthreads();
        sm[threadIdx.x] += t;
        __syncthreads();
    }
    if (gid < NN) rp[gid] = sm[threadIdx.x] - v;   // exclusive
    if (threadIdx.x == SCAN_B - 1) bsum[blockIdx.x] = sm[SCAN_B - 1];
}

__global__ void __launch_bounds__(SCAN_B) scanC_kernel(int* __restrict__ rp,
                                                       const int* __restrict__ bsum,
                                                       int* __restrict__ cursor) {
    __shared__ int sb[128];
    int tid = threadIdx.x;
    if (tid < 128) sb[tid] = (tid < (int)blockIdx.x && tid < NBLK) ? bsum[tid] : 0;
    __syncthreads();
#pragma unroll
    for (int s = 64; s > 0; s >>= 1) {
        if (tid < s) sb[tid] += sb[tid + s];
        __syncthreads();
    }
    int off = sb[0];
    int gid = blockIdx.x * SCAN_B + tid;
    if (gid < NN) {
        int v = rp[gid] + off;
        rp[gid] = v;
        cursor[gid] = v;
    }
    if (gid == 0) rp[NN] = EE;
}

__global__ void __launch_bounds__(256) fill_kernel(const int* __restrict__ ei,
                                                   int* __restrict__ cursor,
                                                   int* __restrict__ csr) {
    int e = blockIdx.x * 256 + threadIdx.x;
    if (e < EE) {
        int d = ei[EE + e];
        int pos = atomicAdd(&cursor[d], 1);
        csr[pos] = ei[e];
    }
}

// ---------------------------------------------------------------------------
// convert x (fp32) -> x16 (fp16); pool exact x into pooled[0]
// ---------------------------------------------------------------------------
__global__ void __launch_bounds__(256) conv_kernel(
    const float* __restrict__ x, const int* __restrict__ batch,
    __half* __restrict__ x16, float* __restrict__ pooled0)
{
    int idx = blockIdx.x * 256 + threadIdx.x;
    int n = idx >> 4;
    int j = (idx & 15) << 2;
    float4 v = *(const float4*)(x + n * DD + j);
    sth4(x16 + n * DD + j, v);
    red4(pooled0 + batch[n] * DD + j, v);
}

// ---------------------------------------------------------------------------
// Fused layer kernel: gather + GEMM1.
// For each of 128 rows: As[r] = (1+eps)*T(u16[n]) + sum_nbr T(u16[nbr]),
// T = relu(alpha*x+beta) from st (null for layer 0 -> identity).
// Also pools T(u16[n]) into pooled_l (if non-null).
// Then Out = As @ W + bias (fp32), fused column stats into st_out.
// ---------------------------------------------------------------------------
constexpr int GEMM_SMEM = (4096 + 128 * 68 + 128 + 128) * 4;  // 52224 B

__global__ void __launch_bounds__(256) gin1_kernel(
    const __half* __restrict__ u16,
    const float* __restrict__ st, const float* __restrict__ gamma,
    const float* __restrict__ beta,
    const int* __restrict__ rowptr, const int* __restrict__ csr,
    const float* __restrict__ eps_l, const int* __restrict__ batch,
    float* __restrict__ pooled_l,
    const float* __restrict__ W, const float* __restrict__ bias,
    float* __restrict__ Out, float* __restrict__ st_out, int nrows)
{
    extern __shared__ float smem[];
    float* Ws = smem;                               // [64][64]
    float (*As)[68] = (float(*)[68])(smem + 4096);  // [128][68]
    float* ab_s = smem + 4096 + 128 * 68;           // [128]
    float* sst  = ab_s + 128;                       // [128]

    const int tid = threadIdx.x;
    const int row0 = blockIdx.x * 128;

    if (tid < 128) sst[tid] = 0.f;
    if (st && tid < 64) {
        const float inv_n = 1.0f / (float)NN;
        float m = st[tid] * inv_n;
        float v = st[64 + tid] * inv_n - m * m;
        float rs = rsqrtf(v + BN_EPS);
        float al = gamma[tid] * rs;
        ab_s[tid] = al;
        ab_s[64 + tid] = beta[tid] - al * m;
    }
    for (int i = tid; i < 1024; i += 256) {
        int k = i >> 4, c = (i & 15) << 2;
        *(float4*)&Ws[k * 64 + c] = *(const float4*)(W + k * 64 + c);
    }
    __syncthreads();

    // -------- gather phase: build As --------
    const float em1 = 1.0f + *eps_l;
    const int j = (tid & 15) << 2;
    float a0 = 1.f, a1 = 1.f, a2 = 1.f, a3 = 1.f, b0 = 0.f, b1 = 0.f, b2 = 0.f, b3 = 0.f;
    if (st) {
        a0 = ab_s[j + 0]; a1 = ab_s[j + 1]; a2 = ab_s[j + 2]; a3 = ab_s[j + 3];
        b0 = ab_s[64 + j + 0]; b1 = ab_s[64 + j + 1];
        b2 = ab_s[64 + j + 2]; b3 = ab_s[64 + j + 3];
    }

#pragma unroll 1
    for (int pass = 0; pass < 8; pass++) {
        int local = pass * 16 + (tid >> 4);
        int n = row0 + local;
        float4 acc = make_float4(0.f, 0.f, 0.f, 0.f);
        if (n < nrows) {
            float4 hv = ldh4(u16 + n * DD + j);
            if (st) hv = bnrelu4(hv, a0, a1, a2, a3, b0, b1, b2, b3);
            if (pooled_l) red4(pooled_l + batch[n] * DD + j, hv);
            acc = make_float4(em1 * hv.x, em1 * hv.y, em1 * hv.z, em1 * hv.w);
            int s = rowptr[n], e = rowptr[n + 1];
            if (st) {
                int i = s;
                for (; i + 2 <= e; i += 2) {
                    int s0 = csr[i], s1 = csr[i + 1];
                    float4 v0 = ldh4(u16 + s0 * DD + j);
                    float4 v1 = ldh4(u16 + s1 * DD + j);
                    v0 = bnrelu4(v0, a0, a1, a2, a3, b0, b1, b2, b3);
                    v1 = bnrelu4(v1, a0, a1, a2, a3, b0, b1, b2, b3);
                    acc.x += v0.x + v1.x; acc.y += v0.y + v1.y;
                    acc.z += v0.z + v1.z; acc.w += v0.w + v1.w;
                }
                for (; i < e; i++) {
                    float4 v = ldh4(u16 + csr[i] * DD + j);
                    v = bnrelu4(v, a0, a1, a2, a3, b0, b1, b2, b3);
                    acc.x += v.x; acc.y += v.y; acc.z += v.z; acc.w += v.w;
                }
            } else {
                int i = s;
                for (; i + 4 <= e; i += 4) {
                    int s0 = csr[i], s1 = csr[i + 1], s2 = csr[i + 2], s3 = csr[i + 3];
                    float4 v0 = ldh4(u16 + s0 * DD + j);
                    float4 v1 = ldh4(u16 + s1 * DD + j);
                    float4 v2 = ldh4(u16 + s2 * DD + j);
                    float4 v3 = ldh4(u16 + s3 * DD + j);
                    acc.x += v0.x + v1.x + v2.x + v3.x;
                    acc.y += v0.y + v1.y + v2.y + v3.y;
                    acc.z += v0.z + v1.z + v2.z + v3.z;
                    acc.w += v0.w + v1.w + v2.w + v3.w;
                }
                for (; i < e; i++) {
                    float4 v = ldh4(u16 + csr[i] * DD + j);
                    acc.x += v.x; acc.y += v.y; acc.z += v.z; acc.w += v.w;
                }
            }
        }
        *(float4*)&As[local][j] = acc;
    }
    __syncthreads();

    // -------- GEMM phase --------
    const int tc = tid & 7;
    const int rg = tid >> 3;
    const int r0 = 4 * rg;

    float2 acc[4][4];
#pragma unroll
    for (int i = 0; i < 4; i++)
#pragma unroll
        for (int jq = 0; jq < 4; jq++) acc[i][jq] = make_float2(0.f, 0.f);

#pragma unroll
    for (int kc = 0; kc < 64; kc += 8) {
        float a[4][8];
#pragma unroll
        for (int rr = 0; rr < 4; rr++) {
            float4 t0 = *(const float4*)&As[r0 + rr][kc];
            float4 t1 = *(const float4*)&As[r0 + rr][kc + 4];
            a[rr][0] = t0.x; a[rr][1] = t0.y; a[rr][2] = t0.z; a[rr][3] = t0.w;
            a[rr][4] = t1.x; a[rr][5] = t1.y; a[rr][6] = t1.z; a[rr][7] = t1.w;
        }
#pragma unroll
        for (int kk = 0; kk < 8; kk++) {
            const float* wr = &Ws[(kc + kk) * 64 + 4 * tc];
            float4 wl = *(const float4*)wr;
            float4 wh = *(const float4*)(wr + 32);
            float2 wl01 = make_float2(wl.x, wl.y), wl23 = make_float2(wl.z, wl.w);
            float2 wh01 = make_float2(wh.x, wh.y), wh23 = make_float2(wh.z, wh.w);
#pragma unroll
            for (int rr = 0; rr < 4; rr++) {
                float2 Av = make_float2(a[rr][kk], a[rr][kk]);
                acc[rr][0] = f2fma(Av, wl01, acc[rr][0]);
                acc[rr][1] = f2fma(Av, wl23, acc[rr][1]);
                acc[rr][2] = f2fma(Av, wh01, acc[rr][2]);
                acc[rr][3] = f2fma(Av, wh23, acc[rr][3]);
            }
        }
    }

    float4 blo = *(const float4*)(bias + 4 * tc);
    float4 bhi = *(const float4*)(bias + 32 + 4 * tc);
    float4 slo = make_float4(0.f, 0.f, 0.f, 0.f), shi = slo, qlo = slo, qhi = slo;
#pragma unroll
    for (int i = 0; i < 4; i++) {
        int gr = row0 + r0 + i;
        if (gr < nrows) {
            float4 o0 = make_float4(acc[i][0].x + blo.x, acc[i][0].y + blo.y,
                                    acc[i][1].x + blo.z, acc[i][1].y + blo.w);
            float4 o1 = make_float4(acc[i][2].x + bhi.x, acc[i][2].y + bhi.y,
                                    acc[i][3].x + bhi.z, acc[i][3].y + bhi.w);
            *(float4*)(Out + gr * 64 + 4 * tc) = o0;
            *(float4*)(Out + gr * 64 + 32 + 4 * tc) = o1;
            slo.x += o0.x; slo.y += o0.y; slo.z += o0.z; slo.w += o0.w;
            shi.x += o1.x; shi.y += o1.y; shi.z += o1.z; shi.w += o1.w;
            qlo.x += o0.x * o0.x; qlo.y += o0.y * o0.y; qlo.z += o0.z * o0.z; qlo.w += o0.w * o0.w;
            qhi.x += o1.x * o1.x; qhi.y += o1.y * o1.y; qhi.z += o1.z * o1.z; qhi.w += o1.w * o1.w;
        }
    }
#pragma unroll
    for (int m = 8; m <= 16; m <<= 1) {
        slo.x += __shfl_xor_sync(~0u, slo.x, m); slo.y += __shfl_xor_sync(~0u, slo.y, m);
        slo.z += __shfl_xor_sync(~0u, slo.z, m); slo.w += __shfl_xor_sync(~0u, slo.w, m);
        shi.x += __shfl_xor_sync(~0u, shi.x, m); shi.y += __shfl_xor_sync(~0u, shi.y, m);
        shi.z += __shfl_xor_sync(~0u, shi.z, m); shi.w += __shfl_xor_sync(~0u, shi.w, m);
        qlo.x += __shfl_xor_sync(~0u, qlo.x, m); qlo.y += __shfl_xor_sync(~0u, qlo.y, m);
        qlo.z += __shfl_xor_sync(~0u, qlo.z, m); qlo.w += __shfl_xor_sync(~0u, qlo.w, m);
        qhi.x += __shfl_xor_sync(~0u, qhi.x, m); qhi.y += __shfl_xor_sync(~0u, qhi.y, m);
        qhi.z += __shfl_xor_sync(~0u, qhi.z, m); qhi.w += __shfl_xor_sync(~0u, qhi.w, m);
    }
    if ((tid & 24) == 0) {
        int c = 4 * tc;
        atomicAdd(&sst[c + 0], slo.x); atomicAdd(&sst[c + 1], slo.y);
        atomicAdd(&sst[c + 2], slo.z); atomicAdd(&sst[c + 3], slo.w);
        atomicAdd(&sst[32 + c + 0], shi.x); atomicAdd(&sst[32 + c + 1], shi.y);
        atomicAdd(&sst[32 + c + 2], shi.z); atomicAdd(&sst[32 + c + 3], shi.w);
        atomicAdd(&sst[64 + c + 0], qlo.x); atomicAdd(&sst[64 + c + 1], qlo.y);
        atomicAdd(&sst[64 + c + 2], qlo.z); atomicAdd(&sst[64 + c + 3], qlo.w);
        atomicAdd(&sst[96 + c + 0], qhi.x); atomicAdd(&sst[96 + c + 1], qhi.y);
        atomicAdd(&sst[96 + c + 2], qhi.z); atomicAdd(&sst[96 + c + 3], qhi.w);
    }
    __syncthreads();
    if (tid < 128) atomicAdd(&st_out[tid], sst[tid]);
}

// ---------------------------------------------------------------------------
// GEMM2: u16 = ( relu(bn(t)) @ W + bias ) stored fp16, fused column stats.
// ---------------------------------------------------------------------------
__global__ void __launch_bounds__(256) gemm2h(
    const float* __restrict__ A, const float* __restrict__ W,
    const float* __restrict__ bias,
    const float* __restrict__ st_in, const float* __restrict__ gamma,
    const float* __restrict__ beta,
    __half* __restrict__ Out, float* __restrict__ st_out, int nrows)
{
    extern __shared__ float smem[];
    float* Ws = smem;
    float (*As)[68] = (float(*)[68])(smem + 4096);
    float* ab_s = smem + 4096 + 128 * 68;
    float* sst  = ab_s + 128;

    const int tid = threadIdx.x;
    const int row0 = blockIdx.x * 128;

    if (tid < 128) sst[tid] = 0.f;
    if (tid < 64) {
        const float inv_n = 1.0f / (float)NN;
        float m = st_in[tid] * inv_n;
        float v = st_in[64 + tid] * inv_n - m * m;
        float rs = rsqrtf(v + BN_EPS);
        float al = gamma[tid] * rs;
        ab_s[tid] = al;
        ab_s[64 + tid] = beta[tid] - al * m;
    }
    for (int i = tid; i < 1024; i += 256) {
        int k = i >> 4, c = (i & 15) << 2;
        *(float4*)&Ws[k * 64 + c] = *(const float4*)(W + k * 64 + c);
    }
    __syncthreads();

    for (int i = tid; i < 2048; i += 256) {
        int r = i >> 4, c = (i & 15) << 2;
        int gr = row0 + r;
        float4 a = make_float4(0.f, 0.f, 0.f, 0.f);
        if (gr < nrows) a = *(const float4*)(A + gr * 64 + c);
        a = bnrelu4(a, ab_s[c + 0], ab_s[c + 1], ab_s[c + 2], ab_s[c + 3],
                    ab_s[64 + c + 0], ab_s[64 + c + 1], ab_s[64 + c + 2], ab_s[64 + c + 3]);
        *(float4*)&As[r][c] = a;
    }
    __syncthreads();

    const int tc = tid & 7;
    const int rg = tid >> 3;
    const int r0 = 4 * rg;

    float2 acc[4][4];
#pragma unroll
    for (int i = 0; i < 4; i++)
#pragma unroll
        for (int jq = 0; jq < 4; jq++) acc[i][jq] = make_float2(0.f, 0.f);

#pragma unroll
    for (int kc = 0; kc < 64; kc += 8) {
        float a[4][8];
#pragma unroll
        for (int rr = 0; rr < 4; rr++) {
            float4 t0 = *(const float4*)&As[r0 + rr][kc];
            float4 t1 = *(const float4*)&As[r0 + rr][kc + 4];
            a[rr][0] = t0.x; a[rr][1] = t0.y; a[rr][2] = t0.z; a[rr][3] = t0.w;
            a[rr][4] = t1.x; a[rr][5] = t1.y; a[rr][6] = t1.z; a[rr][7] = t1.w;
        }
#pragma unroll
        for (int kk = 0; kk < 8; kk++) {
            const float* wr = &Ws[(kc + kk) * 64 + 4 * tc];
            float4 wl = *(const float4*)wr;
            float4 wh = *(const float4*)(wr + 32);
            float2 wl01 = make_float2(wl.x, wl.y), wl23 = make_float2(wl.z, wl.w);
            float2 wh01 = make_float2(wh.x, wh.y), wh23 = make_float2(wh.z, wh.w);
#pragma unroll
            for (int rr = 0; rr < 4; rr++) {
                float2 Av = make_float2(a[rr][kk], a[rr][kk]);
                acc[rr][0] = f2fma(Av, wl01, acc[rr][0]);
                acc[rr][1] = f2fma(Av, wl23, acc[rr][1]);
                acc[rr][2] = f2fma(Av, wh01, acc[rr][2]);
                acc[rr][3] = f2fma(Av, wh23, acc[rr][3]);
            }
        }
    }

    float4 blo = *(const float4*)(bias + 4 * tc);
    float4 bhi = *(const float4*)(bias + 32 + 4 * tc);
    float4 slo = make_float4(0.f, 0.f, 0.f, 0.f), shi = slo, qlo = slo, qhi = slo;
#pragma unroll
    for (int i = 0; i < 4; i++) {
        int gr = row0 + r0 + i;
        if (gr < nrows) {
            float4 o0 = make_float4(acc[i][0].x + blo.x, acc[i][0].y + blo.y,
                                    acc[i][1].x + blo.z, acc[i][1].y + blo.w);
            float4 o1 = make_float4(acc[i][2].x + bhi.x, acc[i][2].y + bhi.y,
                                    acc[i][3].x + bhi.z, acc[i][3].y + bhi.w);
            sth4(Out + gr * 64 + 4 * tc, o0);
            sth4(Out + gr * 64 + 32 + 4 * tc, o1);
            slo.x += o0.x; slo.y += o0.y; slo.z += o0.z; slo.w += o0.w;
            shi.x += o1.x; shi.y += o1.y; shi.z += o1.z; shi.w += o1.w;
            qlo.x += o0.x * o0.x; qlo.y += o0.y * o0.y; qlo.z += o0.z * o0.z; qlo.w += o0.w * o0.w;
            qhi.x += o1.x * o1.x; qhi.y += o1.y * o1.y; qhi.z += o1.z * o1.z; qhi.w += o1.w * o1.w;
        }
    }
#pragma unroll
    for (int m = 8; m <= 16; m <<= 1) {
        slo.x += __shfl_xor_sync(~0u, slo.x, m); slo.y += __shfl_xor_sync(~0u, slo.y, m);
        slo.z += __shfl_xor_sync(~0u, slo.z, m); slo.w += __shfl_xor_sync(~0u, slo.w, m);
        shi.x += __shfl_xor_sync(~0u, shi.x, m); shi.y += __shfl_xor_sync(~0u, shi.y, m);
        shi.z += __shfl_xor_sync(~0u, shi.z, m); shi.w += __shfl_xor_sync(~0u, shi.w, m);
        qlo.x += __shfl_xor_sync(~0u, qlo.x, m); qlo.y += __shfl_xor_sync(~0u, qlo.y, m);
        qlo.z += __shfl_xor_sync(~0u, qlo.z, m); qlo.w += __shfl_xor_sync(~0u, qlo.w, m);
        qhi.x += __shfl_xor_sync(~0u, qhi.x, m); qhi.y += __shfl_xor_sync(~0u, qhi.y, m);
        qhi.z += __shfl_xor_sync(~0u, qhi.z, m); qhi.w += __shfl_xor_sync(~0u, qhi.w, m);
    }
    if ((tid & 24) == 0) {
        int c = 4 * tc;
        atomicAdd(&sst[c + 0], slo.x); atomicAdd(&sst[c + 1], slo.y);
        atomicAdd(&sst[c + 2], slo.z); atomicAdd(&sst[c + 3], slo.w);
        atomicAdd(&sst[32 + c + 0], shi.x); atomicAdd(&sst[32 + c + 1], shi.y);
        atomicAdd(&sst[32 + c + 2], shi.z); atomicAdd(&sst[32 + c + 3], shi.w);
        atomicAdd(&sst[64 + c + 0], qlo.x); atomicAdd(&sst[64 + c + 1], qlo.y);
        atomicAdd(&sst[64 + c + 2], qlo.z); atomicAdd(&sst[64 + c + 3], qlo.w);
        atomicAdd(&sst[96 + c + 0], qhi.x); atomicAdd(&sst[96 + c + 1], qhi.y);
        atomicAdd(&sst[96 + c + 2], qhi.z); atomicAdd(&sst[96 + c + 3], qhi.w);
    }
    __syncthreads();
    if (tid < 128) atomicAdd(&st_out[tid], sst[tid]);
}

// ---------------------------------------------------------------------------
// final-layer pool: pooled += relu(bn(u16))
// ---------------------------------------------------------------------------
__global__ void __launch_bounds__(256) hpool16_kernel(
    const __half* __restrict__ u16, const float* __restrict__ st,
    const float* __restrict__ gamma, const float* __restrict__ beta,
    const int* __restrict__ batch, float* __restrict__ pooled_l)
{
    __shared__ float ab_s[128];
    const int tid = threadIdx.x;
    if (tid < 64) {
        const float inv_n = 1.0f / (float)NN;
        float m = st[tid] * inv_n;
        float v = st[64 + tid] * inv_n - m * m;
        float rs = rsqrtf(v + BN_EPS);
        float al = gamma[tid] * rs;
        ab_s[tid] = al;
        ab_s[64 + tid] = beta[tid] - al * m;
    }
    __syncthreads();
    int idx = blockIdx.x * 256 + tid;
    int n = idx >> 4;
    int j = (idx & 15) << 2;
    float4 v = ldh4(u16 + n * DD + j);
    v = bnrelu4(v, ab_s[j + 0], ab_s[j + 1], ab_s[j + 2], ab_s[j + 3],
                ab_s[64 + j + 0], ab_s[64 + j + 1], ab_s[64 + j + 2], ab_s[64 + j + 3]);
    red4(pooled_l + batch[n] * DD + j, v);
}

// ---------------------------------------------------------------------------
// final readout
// ---------------------------------------------------------------------------
__global__ void score_kernel(const float* __restrict__ pooled,
                             const float* __restrict__ Wp,
                             const float* __restrict__ bp,
                             float* __restrict__ out)
{
    int t = blockIdx.x * 256 + threadIdx.x;
    if (t >= GG * CC) return;
    int g = t / CC, c = t % CC;
    float acc = 0.f;
#pragma unroll
    for (int l = 0; l < LL; l++) {
        acc += bp[l * CC + c];
        const float* pl = pooled + (l * GG + g) * DD;
        const float* wl = Wp + l * DD * CC + c;
        float s = 0.f;
#pragma unroll
        for (int d = 0; d < DD; d++) s += pl[d] * wl[d * CC];
        acc += s;
    }
    out[g * CC + c] = acc;
}

// ---------------------------------------------------------------------------
extern "C" void kernel_launch(void* const* d_in, const int* in_sizes, int n_in,
                              void* d_out, int out_size)
{
    (void)in_sizes; (void)n_in; (void)out_size;
    const float* x     = (const float*)d_in[0];
    const int*   ei    = (const int*)d_in[1];
    const int*   batch = (const int*)d_in[2];
    const float* eps   = (const float*)d_in[3];
    const float* W1    = (const float*)d_in[4];
    const float* b1    = (const float*)d_in[5];
    const float* g1    = (const float*)d_in[6];
    const float* be1   = (const float*)d_in[7];
    const float* W2    = (const float*)d_in[8];
    const float* b2    = (const float*)d_in[9];
    const float* gout  = (const float*)d_in[10];
    const float* beout = (const float*)d_in[11];
    const float* Wp    = (const float*)d_in[12];
    const float* bp    = (const float*)d_in[13];

    __half* u16;
    float *t, *pooled, *stats;
    int *rowptr, *cursor, *csr, *bsum;
    cudaGetSymbolAddress((void**)&u16, g_u16);
    cudaGetSymbolAddress((void**)&t, g_t);
    cudaGetSymbolAddress((void**)&pooled, g_pooled);
    cudaGetSymbolAddress((void**)&stats, g_stats);
    cudaGetSymbolAddress((void**)&rowptr, g_rowptr);
    cudaGetSymbolAddress((void**)&cursor, g_cursor);
    cudaGetSymbolAddress((void**)&csr, g_csr);
    cudaGetSymbolAddress((void**)&bsum, g_bsum);

    static bool attr_set = false;
    if (!attr_set) {
        cudaFuncSetAttribute(gin1_kernel, cudaFuncAttributeMaxDynamicSharedMemorySize,
                             GEMM_SMEM);
        cudaFuncSetAttribute(gemm2h, cudaFuncAttributeMaxDynamicSharedMemorySize,
                             GEMM_SMEM);
        attr_set = true;
    }

    const int HPB = (NN * 16) / 256;          // 6250 (exact)
    const int EB  = (EE + 255) / 256;         // 6250
    const int GMB = (NN + 127) / 128;         // 782

    zerok<<<(LL * GG * DD + 255) / 256, 256>>>(pooled, stats, rowptr);

    // CSR build
    hist_kernel<<<EB, 256>>>(ei, rowptr);
    scanA_kernel<<<NBLK, SCAN_B>>>(rowptr, bsum);
    scanC_kernel<<<NBLK, SCAN_B>>>(rowptr, bsum, cursor);
    fill_kernel<<<EB, 256>>>(ei, cursor, csr);

    // x -> fp16, pool hidden_rep[0] exactly
    conv_kernel<<<HPB, 256>>>(x, batch, u16, pooled);

    for (int l = 0; l < LL - 1; l++) {
        if (l == 0) {
            gin1_kernel<<<GMB, 256, GEMM_SMEM>>>(
                u16, nullptr, nullptr, nullptr, rowptr, csr, eps, batch,
                nullptr, W1, b1, t, stats, NN);
        } else {
            gin1_kernel<<<GMB, 256, GEMM_SMEM>>>(
                u16, stats + (2 * l - 1) * 128, gout + (l - 1) * 64, beout + (l - 1) * 64,
                rowptr, csr, eps + l, batch, pooled + l * GG * DD,
                W1 + l * 4096, b1 + l * 64, t, stats + (2 * l) * 128, NN);
        }
        gemm2h<<<GMB, 256, GEMM_SMEM>>>(
            t, W2 + l * 4096, b2 + l * 64,
            stats + (2 * l) * 128, g1 + l * 64, be1 + l * 64,
            u16, stats + (2 * l + 1) * 128, NN);
    }
    hpool16_kernel<<<HPB, 256>>>(u16, stats + 7 * 128, gout + 3 * 64, beout + 3 * 64,
                                 batch, pooled + 4 * GG * DD);

    score_kernel<<<(GG * CC + 255) / 256, 256>>>(pooled, Wp, bp, (float*)d_out);
}

// round 5
// speedup vs baseline: 1.0657x; 1.0657x over previous
#include <cuda_runtime.h>
#include <cuda_fp16.h>

// Problem constants (fixed by the dataset)
constexpr int NN = 100000;   // nodes
constexpr int EE = 1600000;  // edges
constexpr int DD = 64;       // feature dim
constexpr int GG = 512;      // graphs
constexpr int CC = 10;       // classes
constexpr int LL = 5;        // layers (4 conv layers)
constexpr float BN_EPS = 1e-5f;
constexpr int SCAN_B = 1024;
constexpr int NBLK = (NN + SCAN_B - 1) / SCAN_B;   // 98

// Scratch (device globals; no allocation allowed)
__device__ __align__(16) __half g_u16[NN * DD];   // fp16 activations (x16 at layer 0)
__device__ float g_z[NN * DD];                    // aggregated features (fp32)
__device__ float g_t[NN * DD];                    // GEMM1 output (fp32)
__device__ float g_pooled[LL * GG * DD];
__device__ float g_stats[8 * 128];                // per BN: [0..63]=sum, [64..127]=sumsq
__device__ int   g_rowptr[NN + 1];
__device__ int   g_cursor[NN];
__device__ int   g_csr[EE];
__device__ int   g_bsum[NBLK];

// ---------------------------------------------------------------------------
// helpers
// ---------------------------------------------------------------------------
__device__ __forceinline__ void red4(float* p, float4 v) {
    asm volatile("red.global.add.v4.f32 [%0], {%1,%2,%3,%4};"
                 :: "l"(p), "f"(v.x), "f"(v.y), "f"(v.z), "f"(v.w) : "memory");
}

__device__ __forceinline__ float2 f2fma(float2 a, float2 b, float2 c) {
    float2 d;
    asm("{\n\t"
        ".reg .b64 ra, rb, rc, rd;\n\t"
        "mov.b64 ra, {%2, %3};\n\t"
        "mov.b64 rb, {%4, %5};\n\t"
        "mov.b64 rc, {%6, %7};\n\t"
        "fma.rn.f32x2 rd, ra, rb, rc;\n\t"
        "mov.b64 {%0, %1}, rd;\n\t"
        "}"
        : "=f"(d.x), "=f"(d.y)
        : "f"(a.x), "f"(a.y), "f"(b.x), "f"(b.y), "f"(c.x), "f"(c.y));
    return d;
}

__device__ __forceinline__ float4 ldh4(const __half* p) {
    uint2 r = *(const uint2*)p;
    __half2 a = *(__half2*)&r.x;
    __half2 b = *(__half2*)&r.y;
    float2 fa = __half22float2(a), fb = __half22float2(b);
    return make_float4(fa.x, fa.y, fb.x, fb.y);
}

__device__ __forceinline__ void sth4(__half* p, float4 v) {
    uint2 r;
    *(__half2*)&r.x = __floats2half2_rn(v.x, v.y);
    *(__half2*)&r.y = __floats2half2_rn(v.z, v.w);
    *(uint2*)p = r;
}

__device__ __forceinline__ float4 bnrelu4(float4 v, float a0, float a1, float a2, float a3,
                                          float b0, float b1, float b2, float b3) {
    v.x = fmaxf(fmaf(a0, v.x, b0), 0.f);
    v.y = fmaxf(fmaf(a1, v.y, b1), 0.f);
    v.z = fmaxf(fmaf(a2, v.z, b2), 0.f);
    v.w = fmaxf(fmaf(a3, v.w, b3), 0.f);
    return v;
}

// ---------------------------------------------------------------------------
// zero accumulators + degree counters (reuse g_rowptr as count buffer)
// ---------------------------------------------------------------------------
__global__ void zerok(float* __restrict__ pooled, float* __restrict__ stats,
                      int* __restrict__ cnt) {
    int i = blockIdx.x * 256 + threadIdx.x;
    if (i < LL * GG * DD) pooled[i] = 0.f;
    if (i < 8 * 128) stats[i] = 0.f;
    if (i <= NN) cnt[i] = 0;
}

// ---------------------------------------------------------------------------
// CSR build
// ---------------------------------------------------------------------------
__global__ void __launch_bounds__(256) hist_kernel(const int* __restrict__ ei,
                                                   int* __restrict__ cnt) {
    int e = blockIdx.x * 256 + threadIdx.x;
    if (e < EE) atomicAdd(&cnt[ei[EE + e]], 1);
}

__global__ void __launch_bounds__(SCAN_B) scanA_kernel(int* __restrict__ rp,
                                                       int* __restrict__ bsum) {
    __shared__ int sm[SCAN_B];
    int gid = blockIdx.x * SCAN_B + threadIdx.x;
    int v = (gid < NN) ? rp[gid] : 0;
    sm[threadIdx.x] = v;
    __syncthreads();
    for (int off = 1; off < SCAN_B; off <<= 1) {
        int t = (threadIdx.x >= off) ? sm[threadIdx.x - off] : 0;
        __syncthreads();
        sm[threadIdx.x] += t;
        __syncthreads();
    }
    if (gid < NN) rp[gid] = sm[threadIdx.x] - v;   // exclusive
    if (threadIdx.x == SCAN_B - 1) bsum[blockIdx.x] = sm[SCAN_B - 1];
}

__global__ void __launch_bounds__(SCAN_B) scanC_kernel(int* __restrict__ rp,
                                                       const int* __restrict__ bsum,
                                                       int* __restrict__ cursor) {
    __shared__ int sb[128];
    int tid = threadIdx.x;
    if (tid < 128) sb[tid] = (tid < (int)blockIdx.x && tid < NBLK) ? bsum[tid] : 0;
    __syncthreads();
#pragma unroll
    for (int s = 64; s > 0; s >>= 1) {
        if (tid < s) sb[tid] += sb[tid + s];
        __syncthreads();
    }
    int off = sb[0];
    int gid = blockIdx.x * SCAN_B + tid;
    if (gid < NN) {
        int v = rp[gid] + off;
        rp[gid] = v;
        cursor[gid] = v;
    }
    if (gid == 0) rp[NN] = EE;
}

__global__ void __launch_bounds__(256) fill_kernel(const int* __restrict__ ei,
                                                   int* __restrict__ cursor,
                                                   int* __restrict__ csr) {
    int e = blockIdx.x * 256 + threadIdx.x;
    if (e < EE) {
        int d = ei[EE + e];
        int pos = atomicAdd(&cursor[d], 1);
        csr[pos] = ei[e];
    }
}

// ---------------------------------------------------------------------------
// convert x (fp32) -> x16 (fp16); pool exact x into pooled[0]
// ---------------------------------------------------------------------------
__global__ void __launch_bounds__(256) conv_kernel(
    const float* __restrict__ x, const int* __restrict__ batch,
    __half* __restrict__ x16, float* __restrict__ pooled0)
{
    int idx = blockIdx.x * 256 + threadIdx.x;
    int n = idx >> 4;
    int j = (idx & 15) << 2;
    float4 v = *(const float4*)(x + n * DD + j);
    sth4(x16 + n * DD + j, v);
    red4(pooled0 + batch[n] * DD + j, v);
}

// ---------------------------------------------------------------------------
// gather (fp16 in, fp32 z out): z[n] = (1+eps)*T(u16[n]) + sum_nbr T(u16[nbr])
// T = relu(alpha*x+beta) from st (null -> identity). Pools T(u16[n]) if pooled_l.
// High-occupancy, 16 threads/node. Grid is exact.
// ---------------------------------------------------------------------------
__global__ void __launch_bounds__(256) gather16_kernel(
    const __half* __restrict__ u16,
    const float* __restrict__ st, const float* __restrict__ gamma,
    const float* __restrict__ beta,
    const int* __restrict__ rowptr, const int* __restrict__ csr,
    const float* __restrict__ eps_l, const int* __restrict__ batch,
    float* __restrict__ pooled_l, float* __restrict__ z)
{
    __shared__ float ab_s[128];
    const int tid = threadIdx.x;
    if (st) {
        if (tid < 64) {
            const float inv_n = 1.0f / (float)NN;
            float m = st[tid] * inv_n;
            float v = st[64 + tid] * inv_n - m * m;
            float rs = rsqrtf(v + BN_EPS);
            float al = gamma[tid] * rs;
            ab_s[tid] = al;
            ab_s[64 + tid] = beta[tid] - al * m;
        }
        __syncthreads();
    }
    int idx = blockIdx.x * 256 + tid;
    int n = idx >> 4;
    int j = (idx & 15) << 2;
    int s = rowptr[n];
    int e = rowptr[n + 1];
    float em1 = 1.0f + *eps_l;
    float4 acc;

    if (st) {
        float a0 = ab_s[j + 0], a1 = ab_s[j + 1], a2 = ab_s[j + 2], a3 = ab_s[j + 3];
        float b0 = ab_s[64 + j + 0], b1 = ab_s[64 + j + 1],
              b2 = ab_s[64 + j + 2], b3 = ab_s[64 + j + 3];
        float4 hv = ldh4(u16 + n * DD + j);
        hv = bnrelu4(hv, a0, a1, a2, a3, b0, b1, b2, b3);
        red4(pooled_l + batch[n] * DD + j, hv);
        acc = make_float4(em1 * hv.x, em1 * hv.y, em1 * hv.z, em1 * hv.w);
        int i = s;
        for (; i + 4 <= e; i += 4) {
            int s0 = csr[i], s1 = csr[i + 1], s2 = csr[i + 2], s3 = csr[i + 3];
            float4 v0 = ldh4(u16 + s0 * DD + j);
            float4 v1 = ldh4(u16 + s1 * DD + j);
            float4 v2 = ldh4(u16 + s2 * DD + j);
            float4 v3 = ldh4(u16 + s3 * DD + j);
            v0 = bnrelu4(v0, a0, a1, a2, a3, b0, b1, b2, b3);
            v1 = bnrelu4(v1, a0, a1, a2, a3, b0, b1, b2, b3);
            v2 = bnrelu4(v2, a0, a1, a2, a3, b0, b1, b2, b3);
            v3 = bnrelu4(v3, a0, a1, a2, a3, b0, b1, b2, b3);
            acc.x += v0.x + v1.x + v2.x + v3.x;
            acc.y += v0.y + v1.y + v2.y + v3.y;
            acc.z += v0.z + v1.z + v2.z + v3.z;
            acc.w += v0.w + v1.w + v2.w + v3.w;
        }
        for (; i < e; i++) {
            float4 v = ldh4(u16 + csr[i] * DD + j);
            v = bnrelu4(v, a0, a1, a2, a3, b0, b1, b2, b3);
            acc.x += v.x; acc.y += v.y; acc.z += v.z; acc.w += v.w;
        }
    } else {
        float4 hv = ldh4(u16 + n * DD + j);
        acc = make_float4(em1 * hv.x, em1 * hv.y, em1 * hv.z, em1 * hv.w);
        int i = s;
        for (; i + 4 <= e; i += 4) {
            int s0 = csr[i], s1 = csr[i + 1], s2 = csr[i + 2], s3 = csr[i + 3];
            float4 v0 = ldh4(u16 + s0 * DD + j);
            float4 v1 = ldh4(u16 + s1 * DD + j);
            float4 v2 = ldh4(u16 + s2 * DD + j);
            float4 v3 = ldh4(u16 + s3 * DD + j);
            acc.x += v0.x + v1.x + v2.x + v3.x;
            acc.y += v0.y + v1.y + v2.y + v3.y;
            acc.z += v0.z + v1.z + v2.z + v3.z;
            acc.w += v0.w + v1.w + v2.w + v3.w;
        }
        for (; i < e; i++) {
            float4 v = ldh4(u16 + csr[i] * DD + j);
            acc.x += v.x; acc.y += v.y; acc.z += v.z; acc.w += v.w;
        }
    }
    *(float4*)(z + n * DD + j) = acc;
}

// ---------------------------------------------------------------------------
// GEMM1: t = z @ W + bias (all fp32), fused column stats.
// Block: 256 threads, 128 rows. Thread: 4 rows x 8 cols.
// ---------------------------------------------------------------------------
constexpr int GEMM_SMEM = (4096 + 128 * 68 + 128 + 128) * 4;  // 52224 B

__global__ void __launch_bounds__(256) gemm64(
    const float* __restrict__ A, const float* __restrict__ W,
    const float* __restrict__ bias,
    float* __restrict__ Out, float* __restrict__ st_out, int nrows)
{
    extern __shared__ float smem[];
    float* Ws = smem;                               // [64][64]
    float (*As)[68] = (float(*)[68])(smem + 4096);  // [128][68]
    float* sst  = smem + 4096 + 128 * 68 + 128;     // [128]

    const int tid = threadIdx.x;
    const int row0 = blockIdx.x * 128;

    if (tid < 128) sst[tid] = 0.f;
    for (int i = tid; i < 1024; i += 256) {
        int k = i >> 4, c = (i & 15) << 2;
        *(float4*)&Ws[k * 64 + c] = *(const float4*)(W + k * 64 + c);
    }
    for (int i = tid; i < 2048; i += 256) {
        int r = i >> 4, c = (i & 15) << 2;
        int gr = row0 + r;
        float4 a = make_float4(0.f, 0.f, 0.f, 0.f);
        if (gr < nrows) a = *(const float4*)(A + gr * 64 + c);
        *(float4*)&As[r][c] = a;
    }
    __syncthreads();

    const int tc = tid & 7;
    const int rg = tid >> 3;
    const int r0 = 4 * rg;

    float2 acc[4][4];
#pragma unroll
    for (int i = 0; i < 4; i++)
#pragma unroll
        for (int jq = 0; jq < 4; jq++) acc[i][jq] = make_float2(0.f, 0.f);

#pragma unroll
    for (int kc = 0; kc < 64; kc += 8) {
        float a[4][8];
#pragma unroll
        for (int rr = 0; rr < 4; rr++) {
            float4 t0 = *(const float4*)&As[r0 + rr][kc];
            float4 t1 = *(const float4*)&As[r0 + rr][kc + 4];
            a[rr][0] = t0.x; a[rr][1] = t0.y; a[rr][2] = t0.z; a[rr][3] = t0.w;
            a[rr][4] = t1.x; a[rr][5] = t1.y; a[rr][6] = t1.z; a[rr][7] = t1.w;
        }
#pragma unroll
        for (int kk = 0; kk < 8; kk++) {
            const float* wr = &Ws[(kc + kk) * 64 + 4 * tc];
            float4 wl = *(const float4*)wr;
            float4 wh = *(const float4*)(wr + 32);
            float2 wl01 = make_float2(wl.x, wl.y), wl23 = make_float2(wl.z, wl.w);
            float2 wh01 = make_float2(wh.x, wh.y), wh23 = make_float2(wh.z, wh.w);
#pragma unroll
            for (int rr = 0; rr < 4; rr++) {
                float2 Av = make_float2(a[rr][kk], a[rr][kk]);
                acc[rr][0] = f2fma(Av, wl01, acc[rr][0]);
                acc[rr][1] = f2fma(Av, wl23, acc[rr][1]);
                acc[rr][2] = f2fma(Av, wh01, acc[rr][2]);
                acc[rr][3] = f2fma(Av, wh23, acc[rr][3]);
            }
        }
    }

    float4 blo = *(const float4*)(bias + 4 * tc);
    float4 bhi = *(const float4*)(bias + 32 + 4 * tc);
    float4 slo = make_float4(0.f, 0.f, 0.f, 0.f), shi = slo, qlo = slo, qhi = slo;
#pragma unroll
    for (int i = 0; i < 4; i++) {
        int gr = row0 + r0 + i;
        if (gr < nrows) {
            float4 o0 = make_float4(acc[i][0].x + blo.x, acc[i][0].y + blo.y,
                                    acc[i][1].x + blo.z, acc[i][1].y + blo.w);
            float4 o1 = make_float4(acc[i][2].x + bhi.x, acc[i][2].y + bhi.y,
                                    acc[i][3].x + bhi.z, acc[i][3].y + bhi.w);
            *(float4*)(Out + gr * 64 + 4 * tc) = o0;
            *(float4*)(Out + gr * 64 + 32 + 4 * tc) = o1;
            slo.x += o0.x; slo.y += o0.y; slo.z += o0.z; slo.w += o0.w;
            shi.x += o1.x; shi.y += o1.y; shi.z += o1.z; shi.w += o1.w;
            qlo.x += o0.x * o0.x; qlo.y += o0.y * o0.y; qlo.z += o0.z * o0.z; qlo.w += o0.w * o0.w;
            qhi.x += o1.x * o1.x; qhi.y += o1.y * o1.y; qhi.z += o1.z * o1.z; qhi.w += o1.w * o1.w;
        }
    }
#pragma unroll
    for (int m = 8; m <= 16; m <<= 1) {
        slo.x += __shfl_xor_sync(~0u, slo.x, m); slo.y += __shfl_xor_sync(~0u, slo.y, m);
        slo.z += __shfl_xor_sync(~0u, slo.z, m); slo.w += __shfl_xor_sync(~0u, slo.w, m);
        shi.x += __shfl_xor_sync(~0u, shi.x, m); shi.y += __shfl_xor_sync(~0u, shi.y, m);
        shi.z += __shfl_xor_sync(~0u, shi.z, m); shi.w += __shfl_xor_sync(~0u, shi.w, m);
        qlo.x += __shfl_xor_sync(~0u, qlo.x, m); qlo.y += __shfl_xor_sync(~0u, qlo.y, m);
        qlo.z += __shfl_xor_sync(~0u, qlo.z, m); qlo.w += __shfl_xor_sync(~0u, qlo.w, m);
        qhi.x += __shfl_xor_sync(~0u, qhi.x, m); qhi.y += __shfl_xor_sync(~0u, qhi.y, m);
        qhi.z += __shfl_xor_sync(~0u, qhi.z, m); qhi.w += __shfl_xor_sync(~0u, qhi.w, m);
    }
    if ((tid & 24) == 0) {
        int c = 4 * tc;
        atomicAdd(&sst[c + 0], slo.x); atomicAdd(&sst[c + 1], slo.y);
        atomicAdd(&sst[c + 2], slo.z); atomicAdd(&sst[c + 3], slo.w);
        atomicAdd(&sst[32 + c + 0], shi.x); atomicAdd(&sst[32 + c + 1], shi.y);
        atomicAdd(&sst[32 + c + 2], shi.z); atomicAdd(&sst[32 + c + 3], shi.w);
        atomicAdd(&sst[64 + c + 0], qlo.x); atomicAdd(&sst[64 + c + 1], qlo.y);
        atomicAdd(&sst[64 + c + 2], qlo.z); atomicAdd(&sst[64 + c + 3], qlo.w);
        atomicAdd(&sst[96 + c + 0], qhi.x); atomicAdd(&sst[96 + c + 1], qhi.y);
        atomicAdd(&sst[96 + c + 2], qhi.z); atomicAdd(&sst[96 + c + 3], qhi.w);
    }
    __syncthreads();
    if (tid < 128) atomicAdd(&st_out[tid], sst[tid]);
}

// ---------------------------------------------------------------------------
// GEMM2: u16 = ( relu(bn(t)) @ W + bias ) stored fp16, fused column stats.
// ---------------------------------------------------------------------------
__global__ void __launch_bounds__(256) gemm2h(
    const float* __restrict__ A, const float* __restrict__ W,
    const float* __restrict__ bias,
    const float* __restrict__ st_in, const float* __restrict__ gamma,
    const float* __restrict__ beta,
    __half* __restrict__ Out, float* __restrict__ st_out, int nrows)
{
    extern __shared__ float smem[];
    float* Ws = smem;
    float (*As)[68] = (float(*)[68])(smem + 4096);
    float* ab_s = smem + 4096 + 128 * 68;
    float* sst  = ab_s + 128;

    const int tid = threadIdx.x;
    const int row0 = blockIdx.x * 128;

    if (tid < 128) sst[tid] = 0.f;
    if (tid < 64) {
        const float inv_n = 1.0f / (float)NN;
        float m = st_in[tid] * inv_n;
        float v = st_in[64 + tid] * inv_n - m * m;
        float rs = rsqrtf(v + BN_EPS);
        float al = gamma[tid] * rs;
        ab_s[tid] = al;
        ab_s[64 + tid] = beta[tid] - al * m;
    }
    for (int i = tid; i < 1024; i += 256) {
        int k = i >> 4, c = (i & 15) << 2;
        *(float4*)&Ws[k * 64 + c] = *(const float4*)(W + k * 64 + c);
    }
    __syncthreads();

    for (int i = tid; i < 2048; i += 256) {
        int r = i >> 4, c = (i & 15) << 2;
        int gr = row0 + r;
        float4 a = make_float4(0.f, 0.f, 0.f, 0.f);
        if (gr < nrows) a = *(const float4*)(A + gr * 64 + c);
        a = bnrelu4(a, ab_s[c + 0], ab_s[c + 1], ab_s[c + 2], ab_s[c + 3],
                    ab_s[64 + c + 0], ab_s[64 + c + 1], ab_s[64 + c + 2], ab_s[64 + c + 3]);
        *(float4*)&As[r][c] = a;
    }
    __syncthreads();

    const int tc = tid & 7;
    const int rg = tid >> 3;
    const int r0 = 4 * rg;

    float2 acc[4][4];
#pragma unroll
    for (int i = 0; i < 4; i++)
#pragma unroll
        for (int jq = 0; jq < 4; jq++) acc[i][jq] = make_float2(0.f, 0.f);

#pragma unroll
    for (int kc = 0; kc < 64; kc += 8) {
        float a[4][8];
#pragma unroll
        for (int rr = 0; rr < 4; rr++) {
            float4 t0 = *(const float4*)&As[r0 + rr][kc];
            float4 t1 = *(const float4*)&As[r0 + rr][kc + 4];
            a[rr][0] = t0.x; a[rr][1] = t0.y; a[rr][2] = t0.z; a[rr][3] = t0.w;
            a[rr][4] = t1.x; a[rr][5] = t1.y; a[rr][6] = t1.z; a[rr][7] = t1.w;
        }
#pragma unroll
        for (int kk = 0; kk < 8; kk++) {
            const float* wr = &Ws[(kc + kk) * 64 + 4 * tc];
            float4 wl = *(const float4*)wr;
            float4 wh = *(const float4*)(wr + 32);
            float2 wl01 = make_float2(wl.x, wl.y), wl23 = make_float2(wl.z, wl.w);
            float2 wh01 = make_float2(wh.x, wh.y), wh23 = make_float2(wh.z, wh.w);
#pragma unroll
            for (int rr = 0; rr < 4; rr++) {
                float2 Av = make_float2(a[rr][kk], a[rr][kk]);
                acc[rr][0] = f2fma(Av, wl01, acc[rr][0]);
                acc[rr][1] = f2fma(Av, wl23, acc[rr][1]);
                acc[rr][2] = f2fma(Av, wh01, acc[rr][2]);
                acc[rr][3] = f2fma(Av, wh23, acc[rr][3]);
            }
        }
    }

    float4 blo = *(const float4*)(bias + 4 * tc);
    float4 bhi = *(const float4*)(bias + 32 + 4 * tc);
    float4 slo = make_float4(0.f, 0.f, 0.f, 0.f), shi = slo, qlo = slo, qhi = slo;
#pragma unroll
    for (int i = 0; i < 4; i++) {
        int gr = row0 + r0 + i;
        if (gr < nrows) {
            float4 o0 = make_float4(acc[i][0].x + blo.x, acc[i][0].y + blo.y,
                                    acc[i][1].x + blo.z, acc[i][1].y + blo.w);
            float4 o1 = make_float4(acc[i][2].x + bhi.x, acc[i][2].y + bhi.y,
                                    acc[i][3].x + bhi.z, acc[i][3].y + bhi.w);
            sth4(Out + gr * 64 + 4 * tc, o0);
            sth4(Out + gr * 64 + 32 + 4 * tc, o1);
            slo.x += o0.x; slo.y += o0.y; slo.z += o0.z; slo.w += o0.w;
            shi.x += o1.x; shi.y += o1.y; shi.z += o1.z; shi.w += o1.w;
            qlo.x += o0.x * o0.x; qlo.y += o0.y * o0.y; qlo.z += o0.z * o0.z; qlo.w += o0.w * o0.w;
            qhi.x += o1.x * o1.x; qhi.y += o1.y * o1.y; qhi.z += o1.z * o1.z; qhi.w += o1.w * o1.w;
        }
    }
#pragma unroll
    for (int m = 8; m <= 16; m <<= 1) {
        slo.x += __shfl_xor_sync(~0u, slo.x, m); slo.y += __shfl_xor_sync(~0u, slo.y, m);
        slo.z += __shfl_xor_sync(~0u, slo.z, m); slo.w += __shfl_xor_sync(~0u, slo.w, m);
        shi.x += __shfl_xor_sync(~0u, shi.x, m); shi.y += __shfl_xor_sync(~0u, shi.y, m);
        shi.z += __shfl_xor_sync(~0u, shi.z, m); shi.w += __shfl_xor_sync(~0u, shi.w, m);
        qlo.x += __shfl_xor_sync(~0u, qlo.x, m); qlo.y += __shfl_xor_sync(~0u, qlo.y, m);
        qlo.z += __shfl_xor_sync(~0u, qlo.z, m); qlo.w += __shfl_xor_sync(~0u, qlo.w, m);
        qhi.x += __shfl_xor_sync(~0u, qhi.x, m); qhi.y += __shfl_xor_sync(~0u, qhi.y, m);
        qhi.z += __shfl_xor_sync(~0u, qhi.z, m); qhi.w += __shfl_xor_sync(~0u, qhi.w, m);
    }
    if ((tid & 24) == 0) {
        int c = 4 * tc;
        atomicAdd(&sst[c + 0], slo.x); atomicAdd(&sst[c + 1], slo.y);
        atomicAdd(&sst[c + 2], slo.z); atomicAdd(&sst[c + 3], slo.w);
        atomicAdd(&sst[32 + c + 0], shi.x); atomicAdd(&sst[32 + c + 1], shi.y);
        atomicAdd(&sst[32 + c + 2], shi.z); atomicAdd(&sst[32 + c + 3], shi.w);
        atomicAdd(&sst[64 + c + 0], qlo.x); atomicAdd(&sst[64 + c + 1], qlo.y);
        atomicAdd(&sst[64 + c + 2], qlo.z); atomicAdd(&sst[64 + c + 3], qlo.w);
        atomicAdd(&sst[96 + c + 0], qhi.x); atomicAdd(&sst[96 + c + 1], qhi.y);
        atomicAdd(&sst[96 + c + 2], qhi.z); atomicAdd(&sst[96 + c + 3], qhi.w);
    }
    __syncthreads();
    if (tid < 128) atomicAdd(&st_out[tid], sst[tid]);
}

// ---------------------------------------------------------------------------
// final-layer pool: pooled += relu(bn(u16))
// ---------------------------------------------------------------------------
__global__ void __launch_bounds__(256) hpool16_kernel(
    const __half* __restrict__ u16, const float* __restrict__ st,
    const float* __restrict__ gamma, const float* __restrict__ beta,
    const int* __restrict__ batch, float* __restrict__ pooled_l)
{
    __shared__ float ab_s[128];
    const int tid = threadIdx.x;
    if (tid < 64) {
        const float inv_n = 1.0f / (float)NN;
        float m = st[tid] * inv_n;
        float v = st[64 + tid] * inv_n - m * m;
        float rs = rsqrtf(v + BN_EPS);
        float al = gamma[tid] * rs;
        ab_s[tid] = al;
        ab_s[64 + tid] = beta[tid] - al * m;
    }
    __syncthreads();
    int idx = blockIdx.x * 256 + tid;
    int n = idx >> 4;
    int j = (idx & 15) << 2;
    float4 v = ldh4(u16 + n * DD + j);
    v = bnrelu4(v, ab_s[j + 0], ab_s[j + 1], ab_s[j + 2], ab_s[j + 3],
                ab_s[64 + j + 0], ab_s[64 + j + 1], ab_s[64 + j + 2], ab_s[64 + j + 3]);
    red4(pooled_l + batch[n] * DD + j, v);
}

// ---------------------------------------------------------------------------
// final readout
// ---------------------------------------------------------------------------
__global__ void score_kernel(const float* __restrict__ pooled,
                             const float* __restrict__ Wp,
                             const float* __restrict__ bp,
                             float* __restrict__ out)
{
    int t = blockIdx.x * 256 + threadIdx.x;
    if (t >= GG * CC) return;
    int g = t / CC, c = t % CC;
    float acc = 0.f;
#pragma unroll
    for (int l = 0; l < LL; l++) {
        acc += bp[l * CC + c];
        const float* pl = pooled + (l * GG + g) * DD;
        const float* wl = Wp + l * DD * CC + c;
        float s = 0.f;
#pragma unroll
        for (int d = 0; d < DD; d++) s += pl[d] * wl[d * CC];
        acc += s;
    }
    out[g * CC + c] = acc;
}

// ---------------------------------------------------------------------------
extern "C" void kernel_launch(void* const* d_in, const int* in_sizes, int n_in,
                              void* d_out, int out_size)
{
    (void)in_sizes; (void)n_in; (void)out_size;
    const float* x     = (const float*)d_in[0];
    const int*   ei    = (const int*)d_in[1];
    const int*   batch = (const int*)d_in[2];
    const float* eps   = (const float*)d_in[3];
    const float* W1    = (const float*)d_in[4];
    const float* b1    = (const float*)d_in[5];
    const float* g1    = (const float*)d_in[6];
    const float* be1   = (const float*)d_in[7];
    const float* W2    = (const float*)d_in[8];
    const float* b2    = (const float*)d_in[9];
    const float* gout  = (const float*)d_in[10];
    const float* beout = (const float*)d_in[11];
    const float* Wp    = (const float*)d_in[12];
    const float* bp    = (const float*)d_in[13];

    __half* u16;
    float *z, *t, *pooled, *stats;
    int *rowptr, *cursor, *csr, *bsum;
    cudaGetSymbolAddress((void**)&u16, g_u16);
    cudaGetSymbolAddress((void**)&z, g_z);
    cudaGetSymbolAddress((void**)&t, g_t);
    cudaGetSymbolAddress((void**)&pooled, g_pooled);
    cudaGetSymbolAddress((void**)&stats, g_stats);
    cudaGetSymbolAddress((void**)&rowptr, g_rowptr);
    cudaGetSymbolAddress((void**)&cursor, g_cursor);
    cudaGetSymbolAddress((void**)&csr, g_csr);
    cudaGetSymbolAddress((void**)&bsum, g_bsum);

    static bool attr_set = false;
    if (!attr_set) {
        cudaFuncSetAttribute(gemm64, cudaFuncAttributeMaxDynamicSharedMemorySize,
                             GEMM_SMEM);
        cudaFuncSetAttribute(gemm2h, cudaFuncAttributeMaxDynamicSharedMemorySize,
                             GEMM_SMEM);
        attr_set = true;
    }

    const int HPB = (NN * 16) / 256;          // 6250 (exact)
    const int EB  = (EE + 255) / 256;         // 6250
    const int GMB = (NN + 127) / 128;         // 782

    zerok<<<(LL * GG * DD + 255) / 256, 256>>>(pooled, stats, rowptr);

    // CSR build
    hist_kernel<<<EB, 256>>>(ei, rowptr);
    scanA_kernel<<<NBLK, SCAN_B>>>(rowptr, bsum);
    scanC_kernel<<<NBLK, SCAN_B>>>(rowptr, bsum, cursor);
    fill_kernel<<<EB, 256>>>(ei, cursor, csr);

    // x -> fp16, pool hidden_rep[0] exactly
    conv_kernel<<<HPB, 256>>>(x, batch, u16, pooled);

    for (int l = 0; l < LL - 1; l++) {
        if (l == 0) {
            gather16_kernel<<<HPB, 256>>>(u16, nullptr, nullptr, nullptr,
                                          rowptr, csr, eps, batch, nullptr, z);
        } else {
            gather16_kernel<<<HPB, 256>>>(u16, stats + (2 * l - 1) * 128,
                                          gout + (l - 1) * 64, beout + (l - 1) * 64,
                                          rowptr, csr, eps + l, batch,
                                          pooled + l * GG * DD, z);
        }
        gemm64<<<GMB, 256, GEMM_SMEM>>>(z, W1 + l * 4096, b1 + l * 64,
                                        t, stats + (2 * l) * 128, NN);
        gemm2h<<<GMB, 256, GEMM_SMEM>>>(t, W2 + l * 4096, b2 + l * 64,
                                        stats + (2 * l) * 128, g1 + l * 64, be1 + l * 64,
                                        u16, stats + (2 * l + 1) * 128, NN);
    }
    hpool16_kernel<<<HPB, 256>>>(u16, stats + 7 * 128, gout + 3 * 64, beout + 3 * 64,
                                 batch, pooled + 4 * GG * DD);

    score_kernel<<<(GG * CC + 255) / 256, 256>>>(pooled, Wp, bp, (float*)d_out);
}

// round 6
// speedup vs baseline: 1.4025x; 1.3160x over previous
#include <cuda_runtime.h>
#include <cuda_fp16.h>
#include <mma.h>

using namespace nvcuda;

// Problem constants (fixed by the dataset)
constexpr int NN = 100000;   // nodes
constexpr int EE = 1600000;  // edges
constexpr int DD = 64;       // feature dim
constexpr int GG = 512;      // graphs
constexpr int CC = 10;       // classes
constexpr int LL = 5;        // layers (4 conv layers)
constexpr float BN_EPS = 1e-5f;
constexpr int SCAN_B = 1024;
constexpr int NBLK = (NN + SCAN_B - 1) / SCAN_B;   // 98

// Scratch (device globals; no allocation allowed)
__device__ __align__(16) __half g_u16[NN * DD];   // layer activations (x16 at layer 0)
__device__ __align__(16) __half g_z16[NN * DD];   // aggregated features (fp16)
__device__ __align__(16) __half g_t16[NN * DD];   // GEMM1 output (fp16)
__device__ float g_pooled[LL * GG * DD];
__device__ float g_stats[8 * 128];                // per BN: [0..63]=sum, [64..127]=sumsq
__device__ int   g_rowptr[NN + 1];
__device__ int   g_cursor[NN];
__device__ int   g_csr[EE];
__device__ int   g_bsum[NBLK];

// ---------------------------------------------------------------------------
// helpers
// ---------------------------------------------------------------------------
__device__ __forceinline__ void red4(float* p, float4 v) {
    asm volatile("red.global.add.v4.f32 [%0], {%1,%2,%3,%4};"
                 :: "l"(p), "f"(v.x), "f"(v.y), "f"(v.z), "f"(v.w) : "memory");
}

__device__ __forceinline__ float4 ldh4(const __half* p) {
    uint2 r = *(const uint2*)p;
    __half2 a = *(__half2*)&r.x;
    __half2 b = *(__half2*)&r.y;
    float2 fa = __half22float2(a), fb = __half22float2(b);
    return make_float4(fa.x, fa.y, fb.x, fb.y);
}

__device__ __forceinline__ void sth4(__half* p, float4 v) {
    uint2 r;
    *(__half2*)&r.x = __floats2half2_rn(v.x, v.y);
    *(__half2*)&r.y = __floats2half2_rn(v.z, v.w);
    *(uint2*)p = r;
}

__device__ __forceinline__ float4 bnrelu4(float4 v, float a0, float a1, float a2, float a3,
                                          float b0, float b1, float b2, float b3) {
    v.x = fmaxf(fmaf(a0, v.x, b0), 0.f);
    v.y = fmaxf(fmaf(a1, v.y, b1), 0.f);
    v.z = fmaxf(fmaf(a2, v.z, b2), 0.f);
    v.w = fmaxf(fmaf(a3, v.w, b3), 0.f);
    return v;
}

// ---------------------------------------------------------------------------
// zero accumulators + degree counters (reuse g_rowptr as count buffer)
// ---------------------------------------------------------------------------
__global__ void zerok(float* __restrict__ pooled, float* __restrict__ stats,
                      int* __restrict__ cnt) {
    int i = blockIdx.x * 256 + threadIdx.x;
    if (i < LL * GG * DD) pooled[i] = 0.f;
    if (i < 8 * 128) stats[i] = 0.f;
    if (i <= NN) cnt[i] = 0;
}

// ---------------------------------------------------------------------------
// CSR build
// ---------------------------------------------------------------------------
__global__ void __launch_bounds__(256) hist_kernel(const int* __restrict__ ei,
                                                   int* __restrict__ cnt) {
    int e = blockIdx.x * 256 + threadIdx.x;
    if (e < EE) atomicAdd(&cnt[ei[EE + e]], 1);
}

__global__ void __launch_bounds__(SCAN_B) scanA_kernel(int* __restrict__ rp,
                                                       int* __restrict__ bsum) {
    __shared__ int sm[SCAN_B];
    int gid = blockIdx.x * SCAN_B + threadIdx.x;
    int v = (gid < NN) ? rp[gid] : 0;
    sm[threadIdx.x] = v;
    __syncthreads();
    for (int off = 1; off < SCAN_B; off <<= 1) {
        int t = (threadIdx.x >= off) ? sm[threadIdx.x - off] : 0;
        __syncthreads();
        sm[threadIdx.x] += t;
        __syncthreads();
    }
    if (gid < NN) rp[gid] = sm[threadIdx.x] - v;   // exclusive
    if (threadIdx.x == SCAN_B - 1) bsum[blockIdx.x] = sm[SCAN_B - 1];
}

__global__ void __launch_bounds__(SCAN_B) scanC_kernel(int* __restrict__ rp,
                                                       const int* __restrict__ bsum,
                                                       int* __restrict__ cursor) {
    __shared__ int sb[128];
    int tid = threadIdx.x;
    if (tid < 128) sb[tid] = (tid < (int)blockIdx.x && tid < NBLK) ? bsum[tid] : 0;
    __syncthreads();
#pragma unroll
    for (int s = 64; s > 0; s >>= 1) {
        if (tid < s) sb[tid] += sb[tid + s];
        __syncthreads();
    }
    int off = sb[0];
    int gid = blockIdx.x * SCAN_B + tid;
    if (gid < NN) {
        int v = rp[gid] + off;
        rp[gid] = v;
        cursor[gid] = v;
    }
    if (gid == 0) rp[NN] = EE;
}

__global__ void __launch_bounds__(256) fill_kernel(const int* __restrict__ ei,
                                                   int* __restrict__ cursor,
                                                   int* __restrict__ csr) {
    int e = blockIdx.x * 256 + threadIdx.x;
    if (e < EE) {
        int d = ei[EE + e];
        int pos = atomicAdd(&cursor[d], 1);
        csr[pos] = ei[e];
    }
}

// ---------------------------------------------------------------------------
// convert x (fp32) -> x16 (fp16); pool exact x into pooled[0]
// ---------------------------------------------------------------------------
__global__ void __launch_bounds__(256) conv_kernel(
    const float* __restrict__ x, const int* __restrict__ batch,
    __half* __restrict__ x16, float* __restrict__ pooled0)
{
    int idx = blockIdx.x * 256 + threadIdx.x;
    int n = idx >> 4;
    int j = (idx & 15) << 2;
    float4 v = *(const float4*)(x + n * DD + j);
    sth4(x16 + n * DD + j, v);
    red4(pooled0 + batch[n] * DD + j, v);
}

// ---------------------------------------------------------------------------
// gather (fp16 in, fp16 z out): z[n] = (1+eps)*T(u16[n]) + sum_nbr T(u16[nbr])
// T = relu(alpha*x+beta) from st (null -> identity). Pools T(u16[n]) if pooled_l.
// High-occupancy, 16 threads/node. Grid is exact.
// ---------------------------------------------------------------------------
__global__ void __launch_bounds__(256) gather16_kernel(
    const __half* __restrict__ u16,
    const float* __restrict__ st, const float* __restrict__ gamma,
    const float* __restrict__ beta,
    const int* __restrict__ rowptr, const int* __restrict__ csr,
    const float* __restrict__ eps_l, const int* __restrict__ batch,
    float* __restrict__ pooled_l, __half* __restrict__ z16)
{
    __shared__ float ab_s[128];
    const int tid = threadIdx.x;
    if (st) {
        if (tid < 64) {
            const float inv_n = 1.0f / (float)NN;
            float m = st[tid] * inv_n;
            float v = st[64 + tid] * inv_n - m * m;
            float rs = rsqrtf(v + BN_EPS);
            float al = gamma[tid] * rs;
            ab_s[tid] = al;
            ab_s[64 + tid] = beta[tid] - al * m;
        }
        __syncthreads();
    }
    int idx = blockIdx.x * 256 + tid;
    int n = idx >> 4;
    int j = (idx & 15) << 2;
    int s = rowptr[n];
    int e = rowptr[n + 1];
    float em1 = 1.0f + *eps_l;
    float4 acc;

    if (st) {
        float a0 = ab_s[j + 0], a1 = ab_s[j + 1], a2 = ab_s[j + 2], a3 = ab_s[j + 3];
        float b0 = ab_s[64 + j + 0], b1 = ab_s[64 + j + 1],
              b2 = ab_s[64 + j + 2], b3 = ab_s[64 + j + 3];
        float4 hv = ldh4(u16 + n * DD + j);
        hv = bnrelu4(hv, a0, a1, a2, a3, b0, b1, b2, b3);
        red4(pooled_l + batch[n] * DD + j, hv);
        acc = make_float4(em1 * hv.x, em1 * hv.y, em1 * hv.z, em1 * hv.w);
        int i = s;
        for (; i + 4 <= e; i += 4) {
            int s0 = csr[i], s1 = csr[i + 1], s2 = csr[i + 2], s3 = csr[i + 3];
            float4 v0 = ldh4(u16 + s0 * DD + j);
            float4 v1 = ldh4(u16 + s1 * DD + j);
            float4 v2 = ldh4(u16 + s2 * DD + j);
            float4 v3 = ldh4(u16 + s3 * DD + j);
            v0 = bnrelu4(v0, a0, a1, a2, a3, b0, b1, b2, b3);
            v1 = bnrelu4(v1, a0, a1, a2, a3, b0, b1, b2, b3);
            v2 = bnrelu4(v2, a0, a1, a2, a3, b0, b1, b2, b3);
            v3 = bnrelu4(v3, a0, a1, a2, a3, b0, b1, b2, b3);
            acc.x += v0.x + v1.x + v2.x + v3.x;
            acc.y += v0.y + v1.y + v2.y + v3.y;
            acc.z += v0.z + v1.z + v2.z + v3.z;
            acc.w += v0.w + v1.w + v2.w + v3.w;
        }
        for (; i < e; i++) {
            float4 v = ldh4(u16 + csr[i] * DD + j);
            v = bnrelu4(v, a0, a1, a2, a3, b0, b1, b2, b3);
            acc.x += v.x; acc.y += v.y; acc.z += v.z; acc.w += v.w;
        }
    } else {
        float4 hv = ldh4(u16 + n * DD + j);
        acc = make_float4(em1 * hv.x, em1 * hv.y, em1 * hv.z, em1 * hv.w);
        int i = s;
        for (; i + 4 <= e; i += 4) {
            int s0 = csr[i], s1 = csr[i + 1], s2 = csr[i + 2], s3 = csr[i + 3];
            float4 v0 = ldh4(u16 + s0 * DD + j);
            float4 v1 = ldh4(u16 + s1 * DD + j);
            float4 v2 = ldh4(u16 + s2 * DD + j);
            float4 v3 = ldh4(u16 + s3 * DD + j);
            acc.x += v0.x + v1.x + v2.x + v3.x;
            acc.y += v0.y + v1.y + v2.y + v3.y;
            acc.z += v0.z + v1.z + v2.z + v3.z;
            acc.w += v0.w + v1.w + v2.w + v3.w;
        }
        for (; i < e; i++) {
            float4 v = ldh4(u16 + csr[i] * DD + j);
            acc.x += v.x; acc.y += v.y; acc.z += v.z; acc.w += v.w;
        }
    }
    sth4(z16 + n * DD + j, acc);
}

// ---------------------------------------------------------------------------
// Tensor-core GEMM: OutH[N,64] = T(A16)[N,64] @ W + bias  (fp16 out),
// fused column stats (fp32, computed pre-rounding).
// T = relu(alpha*x+beta) from st_in (null -> identity).
// Block: 256 threads (8 warps), 128 rows; warp computes 16 rows x 64 cols
// via wmma m16n16k16 (fp16 in, fp32 accum).
// ---------------------------------------------------------------------------
struct GemmSmem {
    __half Wh[64 * 72];                              // 9216 B, padded stride 72
    union {
        __half Ah[128 * 72];                         // 18432 B (stage)
        float  Ep[8 * 16 * 64];                      // 32768 B (epilogue)
    } u;
    float ab[128];
    float sst[128];
};

__global__ void __launch_bounds__(256) gemmh_kernel(
    const __half* __restrict__ A16, const float* __restrict__ Wf,
    const float* __restrict__ bias,
    const float* __restrict__ st_in, const float* __restrict__ gamma,
    const float* __restrict__ beta,
    __half* __restrict__ OutH, float* __restrict__ st_out, int nrows)
{
    __shared__ GemmSmem sm;
    const int tid = threadIdx.x;
    const int row0 = blockIdx.x * 128;

    if (tid < 128) sm.sst[tid] = 0.f;
    if (st_in && tid < 64) {
        const float inv_n = 1.0f / (float)NN;
        float m = st_in[tid] * inv_n;
        float v = st_in[64 + tid] * inv_n - m * m;
        float rs = rsqrtf(v + BN_EPS);
        float al = gamma[tid] * rs;
        sm.ab[tid] = al;
        sm.ab[64 + tid] = beta[tid] - al * m;
    }
    // W (fp32 global) -> fp16 smem, stride 72
    for (int i = tid; i < 1024; i += 256) {
        int k = i >> 4, c = (i & 15) << 2;
        float4 w = *(const float4*)(Wf + k * 64 + c);
        uint2 p;
        *(__half2*)&p.x = __floats2half2_rn(w.x, w.y);
        *(__half2*)&p.y = __floats2half2_rn(w.z, w.w);
        *(uint2*)&sm.Wh[k * 72 + c] = p;
    }
    __syncthreads();   // ab ready before staging uses it

    // stage A (fp16 global) -> fp16 smem with optional BN+ReLU
    if (st_in) {
        for (int i = tid; i < 2048; i += 256) {
            int r = i >> 4, c = (i & 15) << 2;
            int gr = row0 + r;
            float4 a = make_float4(0.f, 0.f, 0.f, 0.f);
            if (gr < nrows) {
                a = ldh4(A16 + gr * 64 + c);
                a = bnrelu4(a, sm.ab[c + 0], sm.ab[c + 1], sm.ab[c + 2], sm.ab[c + 3],
                            sm.ab[64 + c + 0], sm.ab[64 + c + 1],
                            sm.ab[64 + c + 2], sm.ab[64 + c + 3]);
            }
            sth4(&sm.u.Ah[r * 72 + c], a);
        }
    } else {
        for (int i = tid; i < 2048; i += 256) {
            int r = i >> 4, c = (i & 15) << 2;
            int gr = row0 + r;
            uint2 val = make_uint2(0u, 0u);
            if (gr < nrows) val = *(const uint2*)(A16 + gr * 64 + c);
            *(uint2*)&sm.u.Ah[r * 72 + c] = val;
        }
    }
    __syncthreads();

    // -------- tensor-core mainloop --------
    const int w = tid >> 5;
    const int lane = tid & 31;

    wmma::fragment<wmma::accumulator, 16, 16, 16, float> cf[4];
#pragma unroll
    for (int n = 0; n < 4; n++) wmma::fill_fragment(cf[n], 0.f);

#pragma unroll
    for (int k = 0; k < 4; k++) {
        wmma::fragment<wmma::matrix_a, 16, 16, 16, __half, wmma::row_major> af;
        wmma::load_matrix_sync(af, &sm.u.Ah[(w * 16) * 72 + k * 16], 72);
#pragma unroll
        for (int n = 0; n < 4; n++) {
            wmma::fragment<wmma::matrix_b, 16, 16, 16, __half, wmma::row_major> bf;
            wmma::load_matrix_sync(bf, &sm.Wh[(k * 16) * 72 + n * 16], 72);
            wmma::mma_sync(cf[n], af, bf, cf[n]);
        }
    }
    __syncthreads();   // Ah no longer needed; Ep aliases it

    float* ep = sm.u.Ep + w * 1024;   // this warp's 16x64 tile
#pragma unroll
    for (int n = 0; n < 4; n++)
        wmma::store_matrix_sync(ep + n * 16, cf[n], 64, wmma::mem_row_major);
    __syncwarp();

    // -------- epilogue: bias, fp16 store, column stats --------
    const int c4 = (lane & 15) << 2;          // fixed column group per lane
    float4 b4 = *(const float4*)(bias + c4);
    float4 s = make_float4(0.f, 0.f, 0.f, 0.f), q = s;
#pragma unroll
    for (int jj = 0; jj < 8; jj++) {
        int r = (lane >> 4) + 2 * jj;         // 0..15
        int gr = row0 + w * 16 + r;
        if (gr < nrows) {
            float4 v = *(const float4*)(ep + r * 64 + c4);
            v.x += b4.x; v.y += b4.y; v.z += b4.z; v.w += b4.w;
            sth4(OutH + gr * 64 + c4, v);
            s.x += v.x; s.y += v.y; s.z += v.z; s.w += v.w;
            q.x += v.x * v.x; q.y += v.y * v.y; q.z += v.z * v.z; q.w += v.w * v.w;
        }
    }
    // lanes l and l+16 share the column group
    s.x += __shfl_xor_sync(~0u, s.x, 16); s.y += __shfl_xor_sync(~0u, s.y, 16);
    s.z += __shfl_xor_sync(~0u, s.z, 16); s.w += __shfl_xor_sync(~0u, s.w, 16);
    q.x += __shfl_xor_sync(~0u, q.x, 16); q.y += __shfl_xor_sync(~0u, q.y, 16);
    q.z += __shfl_xor_sync(~0u, q.z, 16); q.w += __shfl_xor_sync(~0u, q.w, 16);
    if (lane < 16) {
        atomicAdd(&sm.sst[c4 + 0], s.x); atomicAdd(&sm.sst[c4 + 1], s.y);
        atomicAdd(&sm.sst[c4 + 2], s.z); atomicAdd(&sm.sst[c4 + 3], s.w);
        atomicAdd(&sm.sst[64 + c4 + 0], q.x); atomicAdd(&sm.sst[64 + c4 + 1], q.y);
        atomicAdd(&sm.sst[64 + c4 + 2], q.z); atomicAdd(&sm.sst[64 + c4 + 3], q.w);
    }
    __syncthreads();
    if (tid < 128) atomicAdd(&st_out[tid], sm.sst[tid]);
}

// ---------------------------------------------------------------------------
// final-layer pool: pooled += relu(bn(u16))
// ---------------------------------------------------------------------------
__global__ void __launch_bounds__(256) hpool16_kernel(
    const __half* __restrict__ u16, const float* __restrict__ st,
    const float* __restrict__ gamma, const float* __restrict__ beta,
    const int* __restrict__ batch, float* __restrict__ pooled_l)
{
    __shared__ float ab_s[128];
    const int tid = threadIdx.x;
    if (tid < 64) {
        const float inv_n = 1.0f / (float)NN;
        float m = st[tid] * inv_n;
        float v = st[64 + tid] * inv_n - m * m;
        float rs = rsqrtf(v + BN_EPS);
        float al = gamma[tid] * rs;
        ab_s[tid] = al;
        ab_s[64 + tid] = beta[tid] - al * m;
    }
    __syncthreads();
    int idx = blockIdx.x * 256 + tid;
    int n = idx >> 4;
    int j = (idx & 15) << 2;
    float4 v = ldh4(u16 + n * DD + j);
    v = bnrelu4(v, ab_s[j + 0], ab_s[j + 1], ab_s[j + 2], ab_s[j + 3],
                ab_s[64 + j + 0], ab_s[64 + j + 1], ab_s[64 + j + 2], ab_s[64 + j + 3]);
    red4(pooled_l + batch[n] * DD + j, v);
}

// ---------------------------------------------------------------------------
// final readout
// ---------------------------------------------------------------------------
__global__ void score_kernel(const float* __restrict__ pooled,
                             const float* __restrict__ Wp,
                             const float* __restrict__ bp,
                             float* __restrict__ out)
{
    int t = blockIdx.x * 256 + threadIdx.x;
    if (t >= GG * CC) return;
    int g = t / CC, c = t % CC;
    float acc = 0.f;
#pragma unroll
    for (int l = 0; l < LL; l++) {
        acc += bp[l * CC + c];
        const float* pl = pooled + (l * GG + g) * DD;
        const float* wl = Wp + l * DD * CC + c;
        float s = 0.f;
#pragma unroll
        for (int d = 0; d < DD; d++) s += pl[d] * wl[d * CC];
        acc += s;
    }
    out[g * CC + c] = acc;
}

// ---------------------------------------------------------------------------
extern "C" void kernel_launch(void* const* d_in, const int* in_sizes, int n_in,
                              void* d_out, int out_size)
{
    (void)in_sizes; (void)n_in; (void)out_size;
    const float* x     = (const float*)d_in[0];
    const int*   ei    = (const int*)d_in[1];
    const int*   batch = (const int*)d_in[2];
    const float* eps   = (const float*)d_in[3];
    const float* W1    = (const float*)d_in[4];
    const float* b1    = (const float*)d_in[5];
    const float* g1    = (const float*)d_in[6];
    const float* be1   = (const float*)d_in[7];
    const float* W2    = (const float*)d_in[8];
    const float* b2    = (const float*)d_in[9];
    const float* gout  = (const float*)d_in[10];
    const float* beout = (const float*)d_in[11];
    const float* Wp    = (const float*)d_in[12];
    const float* bp    = (const float*)d_in[13];

    __half *u16, *z16, *t16;
    float *pooled, *stats;
    int *rowptr, *cursor, *csr, *bsum;
    cudaGetSymbolAddress((void**)&u16, g_u16);
    cudaGetSymbolAddress((void**)&z16, g_z16);
    cudaGetSymbolAddress((void**)&t16, g_t16);
    cudaGetSymbolAddress((void**)&pooled, g_pooled);
    cudaGetSymbolAddress((void**)&stats, g_stats);
    cudaGetSymbolAddress((void**)&rowptr, g_rowptr);
    cudaGetSymbolAddress((void**)&cursor, g_cursor);
    cudaGetSymbolAddress((void**)&csr, g_csr);
    cudaGetSymbolAddress((void**)&bsum, g_bsum);

    const int HPB = (NN * 16) / 256;          // 6250 (exact)
    const int EB  = (EE + 255) / 256;         // 6250
    const int GMB = (NN + 127) / 128;         // 782

    zerok<<<(LL * GG * DD + 255) / 256, 256>>>(pooled, stats, rowptr);

    // CSR build
    hist_kernel<<<EB, 256>>>(ei, rowptr);
    scanA_kernel<<<NBLK, SCAN_B>>>(rowptr, bsum);
    scanC_kernel<<<NBLK, SCAN_B>>>(rowptr, bsum, cursor);
    fill_kernel<<<EB, 256>>>(ei, cursor, csr);

    // x -> fp16, pool hidden_rep[0] exactly
    conv_kernel<<<HPB, 256>>>(x, batch, u16, pooled);

    for (int l = 0; l < LL - 1; l++) {
        if (l == 0) {
            gather16_kernel<<<HPB, 256>>>(u16, nullptr, nullptr, nullptr,
                                          rowptr, csr, eps, batch, nullptr, z16);
        } else {
            gather16_kernel<<<HPB, 256>>>(u16, stats + (2 * l - 1) * 128,
                                          gout + (l - 1) * 64, beout + (l - 1) * 64,
                                          rowptr, csr, eps + l, batch,
                                          pooled + l * GG * DD, z16);
        }
        // GEMM1: t16 = z16 @ W1 + b1 (no input transform), stats -> 2l
        gemmh_kernel<<<GMB, 256>>>(z16, W1 + l * 4096, b1 + l * 64,
                                   nullptr, nullptr, nullptr,
                                   t16, stats + (2 * l) * 128, NN);
        // GEMM2: u16 = relu(bn(t16)) @ W2 + b2, stats -> 2l+1
        gemmh_kernel<<<GMB, 256>>>(t16, W2 + l * 4096, b2 + l * 64,
                                   stats + (2 * l) * 128, g1 + l * 64, be1 + l * 64,
                                   u16, stats + (2 * l + 1) * 128, NN);
    }
    hpool16_kernel<<<HPB, 256>>>(u16, stats + 7 * 128, gout + 3 * 64, beout + 3 * 64,
                                 batch, pooled + 4 * GG * DD);

    score_kernel<<<(GG * CC + 255) / 256, 256>>>(pooled, Wp, bp, (float*)d_out);
}

// round 7
// speedup vs baseline: 1.4617x; 1.0422x over previous
#include <cuda_runtime.h>
#include <cuda_fp16.h>
#include <mma.h>

using namespace nvcuda;

// Problem constants (fixed by the dataset)
constexpr int NN = 100000;   // nodes
constexpr int EE = 1600000;  // edges
constexpr int DD = 64;       // feature dim
constexpr int GG = 512;      // graphs
constexpr int CC = 10;       // classes
constexpr int LL = 5;        // layers (4 conv layers)
constexpr float BN_EPS = 1e-5f;
constexpr int SCAN_B = 1024;
constexpr int NBLK = (NN + SCAN_B - 1) / SCAN_B;   // 98

// Scratch (device globals; no allocation allowed)
__device__ __align__(16) __half g_u16[NN * DD];   // layer activations (transformed in place)
__device__ __align__(16) __half g_z16[NN * DD];   // aggregated features (fp16)
__device__ __align__(16) __half g_t16[NN * DD];   // GEMM1 output (fp16)
__device__ float g_pooled[LL * GG * DD];
__device__ float g_stats[8 * 128];                // per BN: [0..63]=sum, [64..127]=sumsq
__device__ int   g_rowptr[NN + 1];
__device__ int   g_cursor[NN];
__device__ int   g_csr[EE];
__device__ int   g_bsum[NBLK];

// ---------------------------------------------------------------------------
// helpers
// ---------------------------------------------------------------------------
__device__ __forceinline__ void red4(float* p, float4 v) {
    asm volatile("red.global.add.v4.f32 [%0], {%1,%2,%3,%4};"
                 :: "l"(p), "f"(v.x), "f"(v.y), "f"(v.z), "f"(v.w) : "memory");
}

__device__ __forceinline__ float4 ldh4(const __half* p) {
    uint2 r = *(const uint2*)p;
    __half2 a = *(__half2*)&r.x;
    __half2 b = *(__half2*)&r.y;
    float2 fa = __half22float2(a), fb = __half22float2(b);
    return make_float4(fa.x, fa.y, fb.x, fb.y);
}

__device__ __forceinline__ void sth4(__half* p, float4 v) {
    uint2 r;
    *(__half2*)&r.x = __floats2half2_rn(v.x, v.y);
    *(__half2*)&r.y = __floats2half2_rn(v.z, v.w);
    *(uint2*)p = r;
}

__device__ __forceinline__ float4 bnrelu4(float4 v, float a0, float a1, float a2, float a3,
                                          float b0, float b1, float b2, float b3) {
    v.x = fmaxf(fmaf(a0, v.x, b0), 0.f);
    v.y = fmaxf(fmaf(a1, v.y, b1), 0.f);
    v.z = fmaxf(fmaf(a2, v.z, b2), 0.f);
    v.w = fmaxf(fmaf(a3, v.w, b3), 0.f);
    return v;
}

// ---------------------------------------------------------------------------
// zero accumulators + degree counters (reuse g_rowptr as count buffer)
// ---------------------------------------------------------------------------
__global__ void zerok(float* __restrict__ pooled, float* __restrict__ stats,
                      int* __restrict__ cnt) {
    int i = blockIdx.x * 256 + threadIdx.x;
    if (i < LL * GG * DD) pooled[i] = 0.f;
    if (i < 8 * 128) stats[i] = 0.f;
    if (i <= NN) cnt[i] = 0;
}

// ---------------------------------------------------------------------------
// CSR build
// ---------------------------------------------------------------------------
__global__ void __launch_bounds__(256) hist_kernel(const int* __restrict__ ei,
                                                   int* __restrict__ cnt) {
    int e = blockIdx.x * 256 + threadIdx.x;
    if (e < EE) atomicAdd(&cnt[ei[EE + e]], 1);
}

__global__ void __launch_bounds__(SCAN_B) scanA_kernel(int* __restrict__ rp,
                                                       int* __restrict__ bsum) {
    __shared__ int sm[SCAN_B];
    int gid = blockIdx.x * SCAN_B + threadIdx.x;
    int v = (gid < NN) ? rp[gid] : 0;
    sm[threadIdx.x] = v;
    __syncthreads();
    for (int off = 1; off < SCAN_B; off <<= 1) {
        int t = (threadIdx.x >= off) ? sm[threadIdx.x - off] : 0;
        __syncthreads();
        sm[threadIdx.x] += t;
        __syncthreads();
    }
    if (gid < NN) rp[gid] = sm[threadIdx.x] - v;   // exclusive
    if (threadIdx.x == SCAN_B - 1) bsum[blockIdx.x] = sm[SCAN_B - 1];
}

__global__ void __launch_bounds__(SCAN_B) scanC_kernel(int* __restrict__ rp,
                                                       const int* __restrict__ bsum,
                                                       int* __restrict__ cursor) {
    __shared__ int sb[128];
    int tid = threadIdx.x;
    if (tid < 128) sb[tid] = (tid < (int)blockIdx.x && tid < NBLK) ? bsum[tid] : 0;
    __syncthreads();
#pragma unroll
    for (int s = 64; s > 0; s >>= 1) {
        if (tid < s) sb[tid] += sb[tid + s];
        __syncthreads();
    }
    int off = sb[0];
    int gid = blockIdx.x * SCAN_B + tid;
    if (gid < NN) {
        int v = rp[gid] + off;
        rp[gid] = v;
        cursor[gid] = v;
    }
    if (gid == 0) rp[NN] = EE;
}

__global__ void __launch_bounds__(256) fill_kernel(const int* __restrict__ ei,
                                                   int* __restrict__ cursor,
                                                   int* __restrict__ csr) {
    int e = blockIdx.x * 256 + threadIdx.x;
    if (e < EE) {
        int d = ei[EE + e];
        int pos = atomicAdd(&cursor[d], 1);
        csr[pos] = ei[e];
    }
}

// ---------------------------------------------------------------------------
// convert x (fp32) -> u16 (fp16); pool exact x into pooled[0]
// ---------------------------------------------------------------------------
__global__ void __launch_bounds__(256) conv_kernel(
    const float* __restrict__ x, const int* __restrict__ batch,
    __half* __restrict__ u16, float* __restrict__ pooled0)
{
    int idx = blockIdx.x * 256 + threadIdx.x;
    int n = idx >> 4;
    int j = (idx & 15) << 2;
    float4 v = *(const float4*)(x + n * DD + j);
    sth4(u16 + n * DD + j, v);
    red4(pooled0 + batch[n] * DD + j, v);
}

// ---------------------------------------------------------------------------
// gather (pure fp16 sum): z16[n] = (1+eps)*v16[n] + sum_{nbr} v16[nbr]
// v16 is the already-BN+ReLU'd activation. 16 threads/node, unroll 8. Exact grid.
// ---------------------------------------------------------------------------
__global__ void __launch_bounds__(256) gather16_kernel(
    const __half* __restrict__ v16,
    const int* __restrict__ rowptr, const int* __restrict__ csr,
    const float* __restrict__ eps_l, __half* __restrict__ z16)
{
    int idx = blockIdx.x * 256 + threadIdx.x;
    int n = idx >> 4;
    int j = (idx & 15) << 2;
    int s = rowptr[n];
    int e = rowptr[n + 1];
    float em1 = 1.0f + *eps_l;
    float4 hv = ldh4(v16 + n * DD + j);
    float4 acc = make_float4(em1 * hv.x, em1 * hv.y, em1 * hv.z, em1 * hv.w);

    int i = s;
    for (; i + 8 <= e; i += 8) {
        int s0 = csr[i + 0], s1 = csr[i + 1], s2 = csr[i + 2], s3 = csr[i + 3];
        int s4 = csr[i + 4], s5 = csr[i + 5], s6 = csr[i + 6], s7 = csr[i + 7];
        float4 v0 = ldh4(v16 + s0 * DD + j);
        float4 v1 = ldh4(v16 + s1 * DD + j);
        float4 v2 = ldh4(v16 + s2 * DD + j);
        float4 v3 = ldh4(v16 + s3 * DD + j);
        float4 v4 = ldh4(v16 + s4 * DD + j);
        float4 v5 = ldh4(v16 + s5 * DD + j);
        float4 v6 = ldh4(v16 + s6 * DD + j);
        float4 v7 = ldh4(v16 + s7 * DD + j);
        float4 p0 = make_float4(v0.x + v1.x, v0.y + v1.y, v0.z + v1.z, v0.w + v1.w);
        float4 p1 = make_float4(v2.x + v3.x, v2.y + v3.y, v2.z + v3.z, v2.w + v3.w);
        float4 p2 = make_float4(v4.x + v5.x, v4.y + v5.y, v4.z + v5.z, v4.w + v5.w);
        float4 p3 = make_float4(v6.x + v7.x, v6.y + v7.y, v6.z + v7.z, v6.w + v7.w);
        p0.x += p1.x; p0.y += p1.y; p0.z += p1.z; p0.w += p1.w;
        p2.x += p3.x; p2.y += p3.y; p2.z += p3.z; p2.w += p3.w;
        acc.x += p0.x + p2.x; acc.y += p0.y + p2.y;
        acc.z += p0.z + p2.z; acc.w += p0.w + p2.w;
    }
    for (; i + 2 <= e; i += 2) {
        int s0 = csr[i], s1 = csr[i + 1];
        float4 v0 = ldh4(v16 + s0 * DD + j);
        float4 v1 = ldh4(v16 + s1 * DD + j);
        acc.x += v0.x + v1.x; acc.y += v0.y + v1.y;
        acc.z += v0.z + v1.z; acc.w += v0.w + v1.w;
    }
    if (i < e) {
        float4 v = ldh4(v16 + csr[i] * DD + j);
        acc.x += v.x; acc.y += v.y; acc.z += v.z; acc.w += v.w;
    }
    sth4(z16 + n * DD + j, acc);
}

// ---------------------------------------------------------------------------
// bnapply: u16 = relu(bn(u16)) in place (once per node) + pool into pooled_l
// ---------------------------------------------------------------------------
__global__ void __launch_bounds__(256) bnapply_kernel(
    __half* __restrict__ u16, const float* __restrict__ st,
    const float* __restrict__ gamma, const float* __restrict__ beta,
    const int* __restrict__ batch, float* __restrict__ pooled_l)
{
    __shared__ float ab_s[128];
    const int tid = threadIdx.x;
    if (tid < 64) {
        const float inv_n = 1.0f / (float)NN;
        float m = st[tid] * inv_n;
        float v = st[64 + tid] * inv_n - m * m;
        float rs = rsqrtf(v + BN_EPS);
        float al = gamma[tid] * rs;
        ab_s[tid] = al;
        ab_s[64 + tid] = beta[tid] - al * m;
    }
    __syncthreads();
    int idx = blockIdx.x * 256 + tid;
    int n = idx >> 4;
    int j = (idx & 15) << 2;
    float4 v = ldh4(u16 + n * DD + j);
    v = bnrelu4(v, ab_s[j + 0], ab_s[j + 1], ab_s[j + 2], ab_s[j + 3],
                ab_s[64 + j + 0], ab_s[64 + j + 1], ab_s[64 + j + 2], ab_s[64 + j + 3]);
    sth4(u16 + n * DD + j, v);
    red4(pooled_l + batch[n] * DD + j, v);
}

// ---------------------------------------------------------------------------
// Tensor-core GEMM: OutH[N,64] = T(A16)[N,64] @ W + bias  (fp16 out),
// fused column stats (fp32, computed pre-rounding).
// T = relu(alpha*x+beta) from st_in (null -> identity).
// Block: 256 threads (8 warps), 128 rows; warp computes 16 rows x 64 cols
// via wmma m16n16k16 (fp16 in, fp32 accum).
// ---------------------------------------------------------------------------
struct GemmSmem {
    __half Wh[64 * 72];                              // 9216 B, padded stride 72
    union {
        __half Ah[128 * 72];                         // 18432 B (stage)
        float  Ep[8 * 16 * 64];                      // 32768 B (epilogue)
    } u;
    float ab[128];
    float sst[128];
};

__global__ void __launch_bounds__(256) gemmh_kernel(
    const __half* __restrict__ A16, const float* __restrict__ Wf,
    const float* __restrict__ bias,
    const float* __restrict__ st_in, const float* __restrict__ gamma,
    const float* __restrict__ beta,
    __half* __restrict__ OutH, float* __restrict__ st_out, int nrows)
{
    __shared__ GemmSmem sm;
    const int tid = threadIdx.x;
    const int row0 = blockIdx.x * 128;

    if (tid < 128) sm.sst[tid] = 0.f;
    if (st_in && tid < 64) {
        const float inv_n = 1.0f / (float)NN;
        float m = st_in[tid] * inv_n;
        float v = st_in[64 + tid] * inv_n - m * m;
        float rs = rsqrtf(v + BN_EPS);
        float al = gamma[tid] * rs;
        sm.ab[tid] = al;
        sm.ab[64 + tid] = beta[tid] - al * m;
    }
    // W (fp32 global) -> fp16 smem, stride 72
    for (int i = tid; i < 1024; i += 256) {
        int k = i >> 4, c = (i & 15) << 2;
        float4 w = *(const float4*)(Wf + k * 64 + c);
        uint2 p;
        *(__half2*)&p.x = __floats2half2_rn(w.x, w.y);
        *(__half2*)&p.y = __floats2half2_rn(w.z, w.w);
        *(uint2*)&sm.Wh[k * 72 + c] = p;
    }
    __syncthreads();   // ab ready before staging uses it

    // stage A (fp16 global) -> fp16 smem with optional BN+ReLU
    if (st_in) {
        for (int i = tid; i < 2048; i += 256) {
            int r = i >> 4, c = (i & 15) << 2;
            int gr = row0 + r;
            float4 a = make_float4(0.f, 0.f, 0.f, 0.f);
            if (gr < nrows) {
                a = ldh4(A16 + gr * 64 + c);
                a = bnrelu4(a, sm.ab[c + 0], sm.ab[c + 1], sm.ab[c + 2], sm.ab[c + 3],
                            sm.ab[64 + c + 0], sm.ab[64 + c + 1],
                            sm.ab[64 + c + 2], sm.ab[64 + c + 3]);
            }
            sth4(&sm.u.Ah[r * 72 + c], a);
        }
    } else {
        for (int i = tid; i < 2048; i += 256) {
            int r = i >> 4, c = (i & 15) << 2;
            int gr = row0 + r;
            uint2 val = make_uint2(0u, 0u);
            if (gr < nrows) val = *(const uint2*)(A16 + gr * 64 + c);
            *(uint2*)&sm.u.Ah[r * 72 + c] = val;
        }
    }
    __syncthreads();

    // -------- tensor-core mainloop --------
    const int w = tid >> 5;
    const int lane = tid & 31;

    wmma::fragment<wmma::accumulator, 16, 16, 16, float> cf[4];
#pragma unroll
    for (int n = 0; n < 4; n++) wmma::fill_fragment(cf[n], 0.f);

#pragma unroll
    for (int k = 0; k < 4; k++) {
        wmma::fragment<wmma::matrix_a, 16, 16, 16, __half, wmma::row_major> af;
        wmma::load_matrix_sync(af, &sm.u.Ah[(w * 16) * 72 + k * 16], 72);
#pragma unroll
        for (int n = 0; n < 4; n++) {
            wmma::fragment<wmma::matrix_b, 16, 16, 16, __half, wmma::row_major> bf;
            wmma::load_matrix_sync(bf, &sm.Wh[(k * 16) * 72 + n * 16], 72);
            wmma::mma_sync(cf[n], af, bf, cf[n]);
        }
    }
    __syncthreads();   // Ah no longer needed; Ep aliases it

    float* ep = sm.u.Ep + w * 1024;   // this warp's 16x64 tile
#pragma unroll
    for (int n = 0; n < 4; n++)
        wmma::store_matrix_sync(ep + n * 16, cf[n], 64, wmma::mem_row_major);
    __syncwarp();

    // -------- epilogue: bias, fp16 store, column stats --------
    const int c4 = (lane & 15) << 2;          // fixed column group per lane
    float4 b4 = *(const float4*)(bias + c4);
    float4 s = make_float4(0.f, 0.f, 0.f, 0.f), q = s;
#pragma unroll
    for (int jj = 0; jj < 8; jj++) {
        int r = (lane >> 4) + 2 * jj;         // 0..15
        int gr = row0 + w * 16 + r;
        if (gr < nrows) {
            float4 v = *(const float4*)(ep + r * 64 + c4);
            v.x += b4.x; v.y += b4.y; v.z += b4.z; v.w += b4.w;
            sth4(OutH + gr * 64 + c4, v);
            s.x += v.x; s.y += v.y; s.z += v.z; s.w += v.w;
            q.x += v.x * v.x; q.y += v.y * v.y; q.z += v.z * v.z; q.w += v.w * v.w;
        }
    }
    // lanes l and l+16 share the column group
    s.x += __shfl_xor_sync(~0u, s.x, 16); s.y += __shfl_xor_sync(~0u, s.y, 16);
    s.z += __shfl_xor_sync(~0u, s.z, 16); s.w += __shfl_xor_sync(~0u, s.w, 16);
    q.x += __shfl_xor_sync(~0u, q.x, 16); q.y += __shfl_xor_sync(~0u, q.y, 16);
    q.z += __shfl_xor_sync(~0u, q.z, 16); q.w += __shfl_xor_sync(~0u, q.w, 16);
    if (lane < 16) {
        atomicAdd(&sm.sst[c4 + 0], s.x); atomicAdd(&sm.sst[c4 + 1], s.y);
        atomicAdd(&sm.sst[c4 + 2], s.z); atomicAdd(&sm.sst[c4 + 3], s.w);
        atomicAdd(&sm.sst[64 + c4 + 0], q.x); atomicAdd(&sm.sst[64 + c4 + 1], q.y);
        atomicAdd(&sm.sst[64 + c4 + 2], q.z); atomicAdd(&sm.sst[64 + c4 + 3], q.w);
    }
    __syncthreads();
    if (tid < 128) atomicAdd(&st_out[tid], sm.sst[tid]);
}

// ---------------------------------------------------------------------------
// final readout
// ---------------------------------------------------------------------------
__global__ void score_kernel(const float* __restrict__ pooled,
                             const float* __restrict__ Wp,
                             const float* __restrict__ bp,
                             float* __restrict__ out)
{
    int t = blockIdx.x * 256 + threadIdx.x;
    if (t >= GG * CC) return;
    int g = t / CC, c = t % CC;
    float acc = 0.f;
#pragma unroll
    for (int l = 0; l < LL; l++) {
        acc += bp[l * CC + c];
        const float* pl = pooled + (l * GG + g) * DD;
        const float* wl = Wp + l * DD * CC + c;
        float s = 0.f;
#pragma unroll
        for (int d = 0; d < DD; d++) s += pl[d] * wl[d * CC];
        acc += s;
    }
    out[g * CC + c] = acc;
}

// ---------------------------------------------------------------------------
extern "C" void kernel_launch(void* const* d_in, const int* in_sizes, int n_in,
                              void* d_out, int out_size)
{
    (void)in_sizes; (void)n_in; (void)out_size;
    const float* x     = (const float*)d_in[0];
    const int*   ei    = (const int*)d_in[1];
    const int*   batch = (const int*)d_in[2];
    const float* eps   = (const float*)d_in[3];
    const float* W1    = (const float*)d_in[4];
    const float* b1    = (const float*)d_in[5];
    const float* g1    = (const float*)d_in[6];
    const float* be1   = (const float*)d_in[7];
    const float* W2    = (const float*)d_in[8];
    const float* b2    = (const float*)d_in[9];
    const float* gout  = (const float*)d_in[10];
    const float* beout = (const float*)d_in[11];
    const float* Wp    = (const float*)d_in[12];
    const float* bp    = (const float*)d_in[13];

    __half *u16, *z16, *t16;
    float *pooled, *stats;
    int *rowptr, *cursor, *csr, *bsum;
    cudaGetSymbolAddress((void**)&u16, g_u16);
    cudaGetSymbolAddress((void**)&z16, g_z16);
    cudaGetSymbolAddress((void**)&t16, g_t16);
    cudaGetSymbolAddress((void**)&pooled, g_pooled);
    cudaGetSymbolAddress((void**)&stats, g_stats);
    cudaGetSymbolAddress((void**)&rowptr, g_rowptr);
    cudaGetSymbolAddress((void**)&cursor, g_cursor);
    cudaGetSymbolAddress((void**)&csr, g_csr);
    cudaGetSymbolAddress((void**)&bsum, g_bsum);

    const int HPB = (NN * 16) / 256;          // 6250 (exact)
    const int EB  = (EE + 255) / 256;         // 6250
    const int GMB = (NN + 127) / 128;         // 782

    zerok<<<(LL * GG * DD + 255) / 256, 256>>>(pooled, stats, rowptr);

    // CSR build
    hist_kernel<<<EB, 256>>>(ei, rowptr);
    scanA_kernel<<<NBLK, SCAN_B>>>(rowptr, bsum);
    scanC_kernel<<<NBLK, SCAN_B>>>(rowptr, bsum, cursor);
    fill_kernel<<<EB, 256>>>(ei, cursor, csr);

    // x -> fp16 (identity "transform"), pool hidden_rep[0] exactly
    conv_kernel<<<HPB, 256>>>(x, batch, u16, pooled);

    for (int l = 0; l < LL - 1; l++) {
        // u16 holds the transformed activation h_l (x for l=0)
        gather16_kernel<<<HPB, 256>>>(u16, rowptr, csr, eps + l, z16);
        // GEMM1: t16 = z16 @ W1 + b1 (no input transform), stats -> 2l
        gemmh_kernel<<<GMB, 256>>>(z16, W1 + l * 4096, b1 + l * 64,
                                   nullptr, nullptr, nullptr,
                                   t16, stats + (2 * l) * 128, NN);
        // GEMM2: u16 = relu(bn(t16)) @ W2 + b2, stats -> 2l+1
        gemmh_kernel<<<GMB, 256>>>(t16, W2 + l * 4096, b2 + l * 64,
                                   stats + (2 * l) * 128, g1 + l * 64, be1 + l * 64,
                                   u16, stats + (2 * l + 1) * 128, NN);
        // h_{l+1} = relu(bn(u16)) in place + pool hidden_rep[l+1]
        bnapply_kernel<<<HPB, 256>>>(u16, stats + (2 * l + 1) * 128,
                                     gout + l * 64, beout + l * 64,
                                     batch, pooled + (l + 1) * GG * DD);
    }

    score_kernel<<<(GG * CC + 255) / 256, 256>>>(pooled, Wp, bp, (float*)d_out);
}

// round 8
// speedup vs baseline: 1.5457x; 1.0575x over previous
#include <cuda_runtime.h>
#include <cuda_fp16.h>
#include <mma.h>

using namespace nvcuda;

// Problem constants (fixed by the dataset)
constexpr int NN = 100000;   // nodes
constexpr int EE = 1600000;  // edges
constexpr int DD = 64;       // feature dim
constexpr int GG = 512;      // graphs
constexpr int CC = 10;       // classes
constexpr int LL = 5;        // layers (4 conv layers)
constexpr float BN_EPS = 1e-5f;
constexpr int SCAN_B = 1024;
constexpr int NBLK = (NN + SCAN_B - 1) / SCAN_B;   // 98

// Scratch (device globals; no allocation allowed)
__device__ __align__(16) __half g_u16[NN * DD];   // layer activations (transformed in place)
__device__ __align__(16) __half g_z16[NN * DD];   // aggregated features (fp16)
__device__ __align__(16) __half g_t16[NN * DD];   // GEMM1 output (fp16)
__device__ float g_pooled[LL * GG * DD];
__device__ float g_stats[8 * 128];                // per BN: [0..63]=sum, [64..127]=sumsq
__device__ int   g_rowptr[NN + 1];
__device__ int   g_cursor[NN];
__device__ int   g_csr[EE];
__device__ int   g_bsum[NBLK];

// ---------------------------------------------------------------------------
// helpers
// ---------------------------------------------------------------------------
__device__ __forceinline__ void red4(float* p, float4 v) {
    asm volatile("red.global.add.v4.f32 [%0], {%1,%2,%3,%4};"
                 :: "l"(p), "f"(v.x), "f"(v.y), "f"(v.z), "f"(v.w) : "memory");
}

__device__ __forceinline__ float4 ldh4(const __half* p) {
    uint2 r = *(const uint2*)p;
    __half2 a = *(__half2*)&r.x;
    __half2 b = *(__half2*)&r.y;
    float2 fa = __half22float2(a), fb = __half22float2(b);
    return make_float4(fa.x, fa.y, fb.x, fb.y);
}

__device__ __forceinline__ void sth4(__half* p, float4 v) {
    uint2 r;
    *(__half2*)&r.x = __floats2half2_rn(v.x, v.y);
    *(__half2*)&r.y = __floats2half2_rn(v.z, v.w);
    *(uint2*)p = r;
}

__device__ __forceinline__ float4 bnrelu4(float4 v, float a0, float a1, float a2, float a3,
                                          float b0, float b1, float b2, float b3) {
    v.x = fmaxf(fmaf(a0, v.x, b0), 0.f);
    v.y = fmaxf(fmaf(a1, v.y, b1), 0.f);
    v.z = fmaxf(fmaf(a2, v.z, b2), 0.f);
    v.w = fmaxf(fmaf(a3, v.w, b3), 0.f);
    return v;
}

// accumulate 8 halves (uint4) into 8 fp32 accumulators
__device__ __forceinline__ void acc8(float* a, uint4 r) {
    float2 f0 = __half22float2(*(__half2*)&r.x);
    float2 f1 = __half22float2(*(__half2*)&r.y);
    float2 f2 = __half22float2(*(__half2*)&r.z);
    float2 f3 = __half22float2(*(__half2*)&r.w);
    a[0] += f0.x; a[1] += f0.y; a[2] += f1.x; a[3] += f1.y;
    a[4] += f2.x; a[5] += f2.y; a[6] += f3.x; a[7] += f3.y;
}

// ---------------------------------------------------------------------------
// zero accumulators + degree counters (reuse g_rowptr as count buffer)
// ---------------------------------------------------------------------------
__global__ void zerok(float* __restrict__ pooled, float* __restrict__ stats,
                      int* __restrict__ cnt) {
    int i = blockIdx.x * 256 + threadIdx.x;
    if (i < LL * GG * DD) pooled[i] = 0.f;
    if (i < 8 * 128) stats[i] = 0.f;
    if (i <= NN) cnt[i] = 0;
}

// ---------------------------------------------------------------------------
// CSR build
// ---------------------------------------------------------------------------
__global__ void __launch_bounds__(256) hist_kernel(const int* __restrict__ ei,
                                                   int* __restrict__ cnt) {
    int e = blockIdx.x * 256 + threadIdx.x;
    if (e < EE) atomicAdd(&cnt[ei[EE + e]], 1);
}

__global__ void __launch_bounds__(SCAN_B) scanA_kernel(int* __restrict__ rp,
                                                       int* __restrict__ bsum) {
    __shared__ int sm[SCAN_B];
    int gid = blockIdx.x * SCAN_B + threadIdx.x;
    int v = (gid < NN) ? rp[gid] : 0;
    sm[threadIdx.x] = v;
    __syncthreads();
    for (int off = 1; off < SCAN_B; off <<= 1) {
        int t = (threadIdx.x >= off) ? sm[threadIdx.x - off] : 0;
        __syncthreads();
        sm[threadIdx.x] += t;
        __syncthreads();
    }
    if (gid < NN) rp[gid] = sm[threadIdx.x] - v;   // exclusive
    if (threadIdx.x == SCAN_B - 1) bsum[blockIdx.x] = sm[SCAN_B - 1];
}

__global__ void __launch_bounds__(SCAN_B) scanC_kernel(int* __restrict__ rp,
                                                       const int* __restrict__ bsum,
                                                       int* __restrict__ cursor) {
    __shared__ int sb[128];
    int tid = threadIdx.x;
    if (tid < 128) sb[tid] = (tid < (int)blockIdx.x && tid < NBLK) ? bsum[tid] : 0;
    __syncthreads();
#pragma unroll
    for (int s = 64; s > 0; s >>= 1) {
        if (tid < s) sb[tid] += sb[tid + s];
        __syncthreads();
    }
    int off = sb[0];
    int gid = blockIdx.x * SCAN_B + tid;
    if (gid < NN) {
        int v = rp[gid] + off;
        rp[gid] = v;
        cursor[gid] = v;
    }
    if (gid == 0) rp[NN] = EE;
}

__global__ void __launch_bounds__(256) fill_kernel(const int* __restrict__ ei,
                                                   int* __restrict__ cursor,
                                                   int* __restrict__ csr) {
    int e = blockIdx.x * 256 + threadIdx.x;
    if (e < EE) {
        int d = ei[EE + e];
        int pos = atomicAdd(&cursor[d], 1);
        csr[pos] = ei[e];
    }
}

// ---------------------------------------------------------------------------
// convert x (fp32) -> u16 (fp16); pool exact x into pooled[0]
// ---------------------------------------------------------------------------
__global__ void __launch_bounds__(256) conv_kernel(
    const float* __restrict__ x, const int* __restrict__ batch,
    __half* __restrict__ u16, float* __restrict__ pooled0)
{
    int idx = blockIdx.x * 256 + threadIdx.x;
    int n = idx >> 4;
    int j = (idx & 15) << 2;
    float4 v = *(const float4*)(x + n * DD + j);
    sth4(u16 + n * DD + j, v);
    red4(pooled0 + batch[n] * DD + j, v);
}

// ---------------------------------------------------------------------------
// gather (pure fp16-in fp32-accum sum): z16[n] = (1+eps)*v16[n] + sum_nbr v16[nbr]
// 8 threads/node, each covers 8 halves (16B) via LDG.128. A warp serves 4 nodes:
// per edge only 0.5 LDG warp-instructions (vs 1.0 with 16 threads/node).
// Exact grid: NN*8/256 = 3125 blocks.
// ---------------------------------------------------------------------------
__global__ void __launch_bounds__(256) gather8_kernel(
    const __half* __restrict__ v16,
    const int* __restrict__ rowptr, const int* __restrict__ csr,
    const float* __restrict__ eps_l, __half* __restrict__ z16)
{
    int idx = blockIdx.x * 256 + threadIdx.x;
    int n = idx >> 3;
    int j = (idx & 7) << 3;          // half offset within row
    const __half* row = v16 + n * DD + j;
    int s = rowptr[n];
    int e = rowptr[n + 1];
    float em1 = 1.0f + *eps_l;

    float a[8];
    {
        uint4 r = *(const uint4*)row;
        float2 f0 = __half22float2(*(__half2*)&r.x);
        float2 f1 = __half22float2(*(__half2*)&r.y);
        float2 f2 = __half22float2(*(__half2*)&r.z);
        float2 f3 = __half22float2(*(__half2*)&r.w);
        a[0] = em1 * f0.x; a[1] = em1 * f0.y; a[2] = em1 * f1.x; a[3] = em1 * f1.y;
        a[4] = em1 * f2.x; a[5] = em1 * f2.y; a[6] = em1 * f3.x; a[7] = em1 * f3.y;
    }

    int i = s;
    for (; i + 4 <= e; i += 4) {
        int s0 = csr[i + 0], s1 = csr[i + 1], s2 = csr[i + 2], s3 = csr[i + 3];
        uint4 r0 = *(const uint4*)(v16 + s0 * DD + j);
        uint4 r1 = *(const uint4*)(v16 + s1 * DD + j);
        uint4 r2 = *(const uint4*)(v16 + s2 * DD + j);
        uint4 r3 = *(const uint4*)(v16 + s3 * DD + j);
        acc8(a, r0); acc8(a, r1); acc8(a, r2); acc8(a, r3);
    }
    for (; i < e; i++) {
        uint4 r = *(const uint4*)(v16 + csr[i] * DD + j);
        acc8(a, r);
    }

    uint4 o;
    *(__half2*)&o.x = __floats2half2_rn(a[0], a[1]);
    *(__half2*)&o.y = __floats2half2_rn(a[2], a[3]);
    *(__half2*)&o.z = __floats2half2_rn(a[4], a[5]);
    *(__half2*)&o.w = __floats2half2_rn(a[6], a[7]);
    *(uint4*)(z16 + n * DD + j) = o;
}

// ---------------------------------------------------------------------------
// bnapply: u16 = relu(bn(u16)) in place (once per node) + pool into pooled_l
// ---------------------------------------------------------------------------
__global__ void __launch_bounds__(256) bnapply_kernel(
    __half* __restrict__ u16, const float* __restrict__ st,
    const float* __restrict__ gamma, const float* __restrict__ beta,
    const int* __restrict__ batch, float* __restrict__ pooled_l)
{
    __shared__ float ab_s[128];
    const int tid = threadIdx.x;
    if (tid < 64) {
        const float inv_n = 1.0f / (float)NN;
        float m = st[tid] * inv_n;
        float v = st[64 + tid] * inv_n - m * m;
        float rs = rsqrtf(v + BN_EPS);
        float al = gamma[tid] * rs;
        ab_s[tid] = al;
        ab_s[64 + tid] = beta[tid] - al * m;
    }
    __syncthreads();
    int idx = blockIdx.x * 256 + tid;
    int n = idx >> 4;
    int j = (idx & 15) << 2;
    float4 v = ldh4(u16 + n * DD + j);
    v = bnrelu4(v, ab_s[j + 0], ab_s[j + 1], ab_s[j + 2], ab_s[j + 3],
                ab_s[64 + j + 0], ab_s[64 + j + 1], ab_s[64 + j + 2], ab_s[64 + j + 3]);
    sth4(u16 + n * DD + j, v);
    red4(pooled_l + batch[n] * DD + j, v);
}

// ---------------------------------------------------------------------------
// Tensor-core GEMM: OutH[N,64] = T(A16)[N,64] @ W + bias  (fp16 out),
// fused column stats (fp32, computed pre-rounding).
// T = relu(alpha*x+beta) from st_in (null -> identity).
// ---------------------------------------------------------------------------
struct GemmSmem {
    __half Wh[64 * 72];                              // 9216 B, padded stride 72
    union {
        __half Ah[128 * 72];                         // 18432 B (stage)
        float  Ep[8 * 16 * 64];                      // 32768 B (epilogue)
    } u;
    float ab[128];
    float sst[128];
};

__global__ void __launch_bounds__(256) gemmh_kernel(
    const __half* __restrict__ A16, const float* __restrict__ Wf,
    const float* __restrict__ bias,
    const float* __restrict__ st_in, const float* __restrict__ gamma,
    const float* __restrict__ beta,
    __half* __restrict__ OutH, float* __restrict__ st_out, int nrows)
{
    __shared__ GemmSmem sm;
    const int tid = threadIdx.x;
    const int row0 = blockIdx.x * 128;

    if (tid < 128) sm.sst[tid] = 0.f;
    if (st_in && tid < 64) {
        const float inv_n = 1.0f / (float)NN;
        float m = st_in[tid] * inv_n;
        float v = st_in[64 + tid] * inv_n - m * m;
        float rs = rsqrtf(v + BN_EPS);
        float al = gamma[tid] * rs;
        sm.ab[tid] = al;
        sm.ab[64 + tid] = beta[tid] - al * m;
    }
    // W (fp32 global) -> fp16 smem, stride 72
    for (int i = tid; i < 1024; i += 256) {
        int k = i >> 4, c = (i & 15) << 2;
        float4 w = *(const float4*)(Wf + k * 64 + c);
        uint2 p;
        *(__half2*)&p.x = __floats2half2_rn(w.x, w.y);
        *(__half2*)&p.y = __floats2half2_rn(w.z, w.w);
        *(uint2*)&sm.Wh[k * 72 + c] = p;
    }
    __syncthreads();   // ab ready before staging uses it

    // stage A (fp16 global) -> fp16 smem with optional BN+ReLU
    if (st_in) {
        for (int i = tid; i < 2048; i += 256) {
            int r = i >> 4, c = (i & 15) << 2;
            int gr = row0 + r;
            float4 a = make_float4(0.f, 0.f, 0.f, 0.f);
            if (gr < nrows) {
                a = ldh4(A16 + gr * 64 + c);
                a = bnrelu4(a, sm.ab[c + 0], sm.ab[c + 1], sm.ab[c + 2], sm.ab[c + 3],
                            sm.ab[64 + c + 0], sm.ab[64 + c + 1],
                            sm.ab[64 + c + 2], sm.ab[64 + c + 3]);
            }
            sth4(&sm.u.Ah[r * 72 + c], a);
        }
    } else {
        for (int i = tid; i < 2048; i += 256) {
            int r = i >> 4, c = (i & 15) << 2;
            int gr = row0 + r;
            uint2 val = make_uint2(0u, 0u);
            if (gr < nrows) val = *(const uint2*)(A16 + gr * 64 + c);
            *(uint2*)&sm.u.Ah[r * 72 + c] = val;
        }
    }
    __syncthreads();

    // -------- tensor-core mainloop --------
    const int w = tid >> 5;
    const int lane = tid & 31;

    wmma::fragment<wmma::accumulator, 16, 16, 16, float> cf[4];
#pragma unroll
    for (int n = 0; n < 4; n++) wmma::fill_fragment(cf[n], 0.f);

#pragma unroll
    for (int k = 0; k < 4; k++) {
        wmma::fragment<wmma::matrix_a, 16, 16, 16, __half, wmma::row_major> af;
        wmma::load_matrix_sync(af, &sm.u.Ah[(w * 16) * 72 + k * 16], 72);
#pragma unroll
        for (int n = 0; n < 4; n++) {
            wmma::fragment<wmma::matrix_b, 16, 16, 16, __half, wmma::row_major> bf;
            wmma::load_matrix_sync(bf, &sm.Wh[(k * 16) * 72 + n * 16], 72);
            wmma::mma_sync(cf[n], af, bf, cf[n]);
        }
    }
    __syncthreads();   // Ah no longer needed; Ep aliases it

    float* ep = sm.u.Ep + w * 1024;   // this warp's 16x64 tile
#pragma unroll
    for (int n = 0; n < 4; n++)
        wmma::store_matrix_sync(ep + n * 16, cf[n], 64, wmma::mem_row_major);
    __syncwarp();

    // -------- epilogue: bias, fp16 store, column stats --------
    const int c4 = (lane & 15) << 2;          // fixed column group per lane
    float4 b4 = *(const float4*)(bias + c4);
    float4 s = make_float4(0.f, 0.f, 0.f, 0.f), q = s;
#pragma unroll
    for (int jj = 0; jj < 8; jj++) {
        int r = (lane >> 4) + 2 * jj;         // 0..15
        int gr = row0 + w * 16 + r;
        if (gr < nrows) {
            float4 v = *(const float4*)(ep + r * 64 + c4);
            v.x += b4.x; v.y += b4.y; v.z += b4.z; v.w += b4.w;
            sth4(OutH + gr * 64 + c4, v);
            s.x += v.x; s.y += v.y; s.z += v.z; s.w += v.w;
            q.x += v.x * v.x; q.y += v.y * v.y; q.z += v.z * v.z; q.w += v.w * v.w;
        }
    }
    // lanes l and l+16 share the column group
    s.x += __shfl_xor_sync(~0u, s.x, 16); s.y += __shfl_xor_sync(~0u, s.y, 16);
    s.z += __shfl_xor_sync(~0u, s.z, 16); s.w += __shfl_xor_sync(~0u, s.w, 16);
    q.x += __shfl_xor_sync(~0u, q.x, 16); q.y += __shfl_xor_sync(~0u, q.y, 16);
    q.z += __shfl_xor_sync(~0u, q.z, 16); q.w += __shfl_xor_sync(~0u, q.w, 16);
    if (lane < 16) {
        atomicAdd(&sm.sst[c4 + 0], s.x); atomicAdd(&sm.sst[c4 + 1], s.y);
        atomicAdd(&sm.sst[c4 + 2], s.z); atomicAdd(&sm.sst[c4 + 3], s.w);
        atomicAdd(&sm.sst[64 + c4 + 0], q.x); atomicAdd(&sm.sst[64 + c4 + 1], q.y);
        atomicAdd(&sm.sst[64 + c4 + 2], q.z); atomicAdd(&sm.sst[64 + c4 + 3], q.w);
    }
    __syncthreads();
    if (tid < 128) atomicAdd(&st_out[tid], sm.sst[tid]);
}

// ---------------------------------------------------------------------------
// final readout
// ---------------------------------------------------------------------------
__global__ void score_kernel(const float* __restrict__ pooled,
                             const float* __restrict__ Wp,
                             const float* __restrict__ bp,
                             float* __restrict__ out)
{
    int t = blockIdx.x * 256 + threadIdx.x;
    if (t >= GG * CC) return;
    int g = t / CC, c = t % CC;
    float acc = 0.f;
#pragma unroll
    for (int l = 0; l < LL; l++) {
        acc += bp[l * CC + c];
        const float* pl = pooled + (l * GG + g) * DD;
        const float* wl = Wp + l * DD * CC + c;
        float s = 0.f;
#pragma unroll
        for (int d = 0; d < DD; d++) s += pl[d] * wl[d * CC];
        acc += s;
    }
    out[g * CC + c] = acc;
}

// ---------------------------------------------------------------------------
extern "C" void kernel_launch(void* const* d_in, const int* in_sizes, int n_in,
                              void* d_out, int out_size)
{
    (void)in_sizes; (void)n_in; (void)out_size;
    const float* x     = (const float*)d_in[0];
    const int*   ei    = (const int*)d_in[1];
    const int*   batch = (const int*)d_in[2];
    const float* eps   = (const float*)d_in[3];
    const float* W1    = (const float*)d_in[4];
    const float* b1    = (const float*)d_in[5];
    const float* g1    = (const float*)d_in[6];
    const float* be1   = (const float*)d_in[7];
    const float* W2    = (const float*)d_in[8];
    const float* b2    = (const float*)d_in[9];
    const float* gout  = (const float*)d_in[10];
    const float* beout = (const float*)d_in[11];
    const float* Wp    = (const float*)d_in[12];
    const float* bp    = (const float*)d_in[13];

    __half *u16, *z16, *t16;
    float *pooled, *stats;
    int *rowptr, *cursor, *csr, *bsum;
    cudaGetSymbolAddress((void**)&u16, g_u16);
    cudaGetSymbolAddress((void**)&z16, g_z16);
    cudaGetSymbolAddress((void**)&t16, g_t16);
    cudaGetSymbolAddress((void**)&pooled, g_pooled);
    cudaGetSymbolAddress((void**)&stats, g_stats);
    cudaGetSymbolAddress((void**)&rowptr, g_rowptr);
    cudaGetSymbolAddress((void**)&cursor, g_cursor);
    cudaGetSymbolAddress((void**)&csr, g_csr);
    cudaGetSymbolAddress((void**)&bsum, g_bsum);

    const int HPB  = (NN * 16) / 256;         // 6250 (exact, 16 thr/node kernels)
    const int HPB8 = (NN * 8) / 256;          // 3125 (exact, 8 thr/node gather)
    const int EB   = (EE + 255) / 256;        // 6250
    const int GMB  = (NN + 127) / 128;        // 782

    zerok<<<(LL * GG * DD + 255) / 256, 256>>>(pooled, stats, rowptr);

    // CSR build
    hist_kernel<<<EB, 256>>>(ei, rowptr);
    scanA_kernel<<<NBLK, SCAN_B>>>(rowptr, bsum);
    scanC_kernel<<<NBLK, SCAN_B>>>(rowptr, bsum, cursor);
    fill_kernel<<<EB, 256>>>(ei, cursor, csr);

    // x -> fp16 (identity "transform"), pool hidden_rep[0] exactly
    conv_kernel<<<HPB, 256>>>(x, batch, u16, pooled);

    for (int l = 0; l < LL - 1; l++) {
        // u16 holds the transformed activation h_l (x for l=0)
        gather8_kernel<<<HPB8, 256>>>(u16, rowptr, csr, eps + l, z16);
        // GEMM1: t16 = z16 @ W1 + b1 (no input transform), stats -> 2l
        gemmh_kernel<<<GMB, 256>>>(z16, W1 + l * 4096, b1 + l * 64,
                                   nullptr, nullptr, nullptr,
                                   t16, stats + (2 * l) * 128, NN);
        // GEMM2: u16 = relu(bn(t16)) @ W2 + b2, stats -> 2l+1
        gemmh_kernel<<<GMB, 256>>>(t16, W2 + l * 4096, b2 + l * 64,
                                   stats + (2 * l) * 128, g1 + l * 64, be1 + l * 64,
                                   u16, stats + (2 * l + 1) * 128, NN);
        // h_{l+1} = relu(bn(u16)) in place + pool hidden_rep[l+1]
        bnapply_kernel<<<HPB, 256>>>(u16, stats + (2 * l + 1) * 128,
                                     gout + l * 64, beout + l * 64,
                                     batch, pooled + (l + 1) * GG * DD);
    }

    score_kernel<<<(GG * CC + 255) / 256, 256>>>(pooled, Wp, bp, (float*)d_out);
}